// round 3
// baseline (speedup 1.0000x reference)
#include <cuda_runtime.h>

// Problem constants (from reference): bs=1024, n=64, d=2, nc=32
#define NPART 64
#define ND    128          // n*d
#define NC    32
#define M4    128          // 4*nc
#define NROW  96           // 3*nc active G rows
#define REG   1e-3f

// Precomputed W = (Minv^{-1} + reg I)^{-1} = (I + reg*Minv)^{-1} Minv  (64x64, batch-shared)
__device__ float g_W[NPART * NPART];

// ---------------------------------------------------------------------------
// Kernel A: one CTA, Gauss-Jordan invert B = I + reg*Minv (extremely well
// conditioned, eig in [1, ~1.01], no pivoting needed), then W = Binv * Minv.
// ---------------------------------------------------------------------------
__global__ void prep_W_kernel(const float* __restrict__ Minv) {
    __shared__ float aug[64][128];   // [B | I]
    __shared__ float fac[64];
    __shared__ float s_invp;
    int tid = threadIdx.x;

    for (int idx = tid; idx < 64 * 128; idx += blockDim.x) {
        int r = idx >> 7, c = idx & 127;
        float val;
        if (c < 64) val = REG * Minv[r * 64 + c] + ((r == c) ? 1.f : 0.f);
        else        val = ((c - 64) == r) ? 1.f : 0.f;
        aug[r][c] = val;
    }
    __syncthreads();

    for (int k = 0; k < 64; k++) {
        if (tid == 0) s_invp = 1.f / aug[k][k];
        __syncthreads();
        float invp = s_invp;
        for (int c = tid; c < 128; c += blockDim.x) aug[k][c] *= invp;
        __syncthreads();
        if (tid < 64) fac[tid] = aug[tid][k];
        __syncthreads();
        for (int idx = tid; idx < 64 * 128; idx += blockDim.x) {
            int r = idx >> 7, c = idx & 127;
            if (r != k) aug[r][c] -= fac[r] * aug[k][c];
        }
        __syncthreads();
    }

    // W = Binv @ Minv  (Binv and Minv commute; result symmetric)
    for (int idx = tid; idx < 64 * 64; idx += blockDim.x) {
        int p = idx >> 6, q = idx & 63;
        float s = 0.f;
        for (int b = 0; b < 64; b++) s += aug[p][64 + b] * Minv[b * 64 + q];
        g_W[idx] = s;
    }
}

// ---------------------------------------------------------------------------
// Kernel B: one CTA (256 threads) per batch element.
// Builds the 128x128 Schur complement S in smem, LU-factorizes with partial
// pivoting, back-substitutes, and reconstructs v_plus via two small matvecs.
// ---------------------------------------------------------------------------
__global__ void __launch_bounds__(256, 1)
solve_batch_kernel(const float* __restrict__ x, const float* __restrict__ v,
                   const int* __restrict__ cld, const float* __restrict__ dist,
                   const float* __restrict__ mu, const float* __restrict__ cor,
                   float* __restrict__ out) {
    extern __shared__ float S[];          // 128 * 129 floats = 66048 B

    __shared__ float kappa[NC][NC];       // 4 KB
    __shared__ float en[NC][2], et[NC][2];
    __shared__ int   ii[NC], jj[NC];
    __shared__ float hs[NC], mus[NC];
    __shared__ float vs[NPART][2];
    __shared__ float ys[NPART][2];
    __shared__ float rhs[M4];
    __shared__ float gacc[NPART][2];
    __shared__ int   s_piv;
    __shared__ float warp_bv[8];
    __shared__ int   warp_bi[8];

    const int b   = blockIdx.x;
    const int tid = threadIdx.x;
    const float* xb = x + b * ND;
    const float* vb = v + b * ND;

    // ---- load + per-contact geometry -------------------------------------
    if (tid < 128) {
        out[b * 256 + tid] = xb[tid];            // x passes through unchanged
        vs[tid >> 1][tid & 1] = vb[tid];
    }
    if (tid < NC) {
        int c = tid;
        int i = cld[b * (NC * 2) + c * 2 + 0];
        int j = cld[b * (NC * 2) + c * 2 + 1];
        ii[c] = i; jj[c] = j;
        float dx = xb[j * 2 + 0] - xb[i * 2 + 0];
        float dy = xb[j * 2 + 1] - xb[i * 2 + 1];
        float inv = rsqrtf(dx * dx + dy * dy);
        float ex = dx * inv, ey = dy * inv;
        en[c][0] = ex;  en[c][1] = ey;
        et[c][0] = -ey; et[c][1] = ex;
        // Jcnv = e_n . (v_j - v_i)
        float jv = ex * (vb[j * 2] - vb[i * 2]) + ey * (vb[j * 2 + 1] - vb[i * 2 + 1]);
        // h = min(dist/(DT*8), cor * Jcnv);  DT*8 = 0.08 -> *12.5
        hs[c]  = fminf(dist[b * NC + c] * 12.5f, cor[b * NC + c] * jv);
        mus[c] = mu[b * NC + c];
    }
    __syncthreads();

    // ---- kappa[cr][cs] = W[ii,is] - W[ii,js] - W[ji,is] + W[ji,js] --------
    for (int idx = tid; idx < NC * NC; idx += 256) {
        int cr = idx >> 5, cs = idx & 31;
        int ir = ii[cr], jr = jj[cr], is = ii[cs], js = jj[cs];
        kappa[cr][cs] = g_W[ir * 64 + is] - g_W[ir * 64 + js]
                      - g_W[jr * 64 + is] + g_W[jr * 64 + js];
    }

    // ---- y = A^{-1} r1 = -v + reg * (W v) ---------------------------------
    if (tid < 128) {
        int p = tid >> 1, s2 = tid & 1;
        float acc = 0.f;
        #pragma unroll 8
        for (int q = 0; q < 64; q++) acc += g_W[p * 64 + q] * vs[q][s2];
        ys[p][s2] = -vs[p][s2] + REG * acc;
    }
    __syncthreads();

    // ---- build S = D - G A^{-1} G^T + reg I ------------------------------
    for (int idx = tid; idx < M4 * M4; idx += 256) {
        int r = idx >> 7, s = idx & 127;
        float val;
        if (r < NROW && s < NROW) {
            int cr, cs; float drx, dry, dsx, dsy;
            if (r < NC) { cr = r; drx = en[r][0]; dry = en[r][1]; }
            else { int q = (r - NC) >> 1; cr = q;
                   float sg = ((r - NC) & 1) ? -1.f : 1.f;
                   drx = sg * et[q][0]; dry = sg * et[q][1]; }
            if (s < NC) { cs = s; dsx = en[s][0]; dsy = en[s][1]; }
            else { int q = (s - NC) >> 1; cs = q;
                   float sg = ((s - NC) & 1) ? -1.f : 1.f;
                   dsx = sg * et[q][0]; dsy = sg * et[q][1]; }
            val = -(drx * dsx + dry * dsy) * kappa[cr][cs];
            if (r == s) val += REG;
        } else if (r < NC) {
            val = 0.f;                                    // D rows 0..nc are empty
        } else if (r < NROW) {
            int q = (r - NC) >> 1;                        // -E block
            val = (q == s - NROW) ? -1.f : 0.f;
        } else {
            int q = r - NROW;
            if (s < NC)        val = (s == q) ? -mus[q] : 0.f;   // -diag(mu)
            else if (s < NROW) val = (((s - NC) >> 1) == q) ? 1.f : 0.f; // +E^T
            else               val = (s - NROW == q) ? REG : 0.f;
        }
        S[r * 129 + s] = val;
    }

    // ---- rhs = r2 - G y = -h - (d_r . (y_j - y_i)) ------------------------
    if (tid < 128) {
        int r = tid;
        float val = 0.f;
        if (r < NC) {
            float dx = ys[jj[r]][0] - ys[ii[r]][0];
            float dy = ys[jj[r]][1] - ys[ii[r]][1];
            val = -hs[r] - (en[r][0] * dx + en[r][1] * dy);
        } else if (r < NROW) {
            int q = (r - NC) >> 1;
            float sg = ((r - NC) & 1) ? -1.f : 1.f;
            float dx = ys[jj[q]][0] - ys[ii[q]][0];
            float dy = ys[jj[q]][1] - ys[ii[q]][1];
            val = -sg * (et[q][0] * dx + et[q][1] * dy);
        }
        rhs[r] = val;
    }
    __syncthreads();

    // ---- LU with partial pivoting in smem ---------------------------------
    for (int k = 0; k < M4; k++) {
        // argmax |S[r][k]| over r in [k,128)
        float bv = -1.f; int bi = k;
        if (tid < 128 && tid >= k) { bv = fabsf(S[tid * 129 + k]); bi = tid; }
        for (int off = 16; off; off >>= 1) {
            float ov = __shfl_down_sync(0xffffffffu, bv, off);
            int   oi = __shfl_down_sync(0xffffffffu, bi, off);
            if (ov > bv) { bv = ov; bi = oi; }
        }
        if ((tid & 31) == 0) { warp_bv[tid >> 5] = bv; warp_bi[tid >> 5] = bi; }
        __syncthreads();
        if (tid == 0) {
            float bb = warp_bv[0]; int bbi = warp_bi[0];
            for (int w = 1; w < 4; w++)
                if (warp_bv[w] > bb) { bb = warp_bv[w]; bbi = warp_bi[w]; }
            s_piv = bbi;
        }
        __syncthreads();
        int piv = s_piv;                       // uniform across block
        if (piv != k) {
            if (tid < 128) {
                float t = S[k * 129 + tid];
                S[k * 129 + tid]   = S[piv * 129 + tid];
                S[piv * 129 + tid] = t;
            }
            if (tid == 128) { float t = rhs[k]; rhs[k] = rhs[piv]; rhs[piv] = t; }
            __syncthreads();
        }
        // eliminate: 2 threads per row, interleaved columns
        int r = tid & 127, half = tid >> 7;
        if (r > k) {
            float m = S[r * 129 + k] / S[k * 129 + k];
            if (half == 0) rhs[r] -= m * rhs[k];
            for (int j = k + 1 + half; j < 128; j += 2)
                S[r * 129 + j] -= m * S[k * 129 + j];
        }
        __syncthreads();
    }

    // ---- back substitution -------------------------------------------------
    for (int k = M4 - 1; k >= 0; k--) {
        if (tid == 0) rhs[k] = rhs[k] / S[k * 129 + k];
        __syncthreads();
        float lk = rhs[k];
        if (tid < k) rhs[tid] -= S[tid * 129 + k] * lk;
        __syncthreads();
    }
    // rhs now holds l

    // ---- g = G^T l  (sparse scatter, smem atomics) -------------------------
    if (tid < 128) gacc[tid >> 1][tid & 1] = 0.f;
    __syncthreads();
    if (tid < NC) {
        int c = tid;
        float wn = rhs[c];
        float wt = rhs[NC + 2 * c] - rhs[NC + 2 * c + 1];
        float wx = wn * en[c][0] + wt * et[c][0];
        float wy = wn * en[c][1] + wt * et[c][1];
        atomicAdd(&gacc[ii[c]][0], -wx);
        atomicAdd(&gacc[ii[c]][1], -wy);
        atomicAdd(&gacc[jj[c]][0],  wx);
        atomicAdd(&gacc[jj[c]][1],  wy);
    }
    __syncthreads();

    // ---- v_plus = v + W (g - reg*v) ----------------------------------------
    if (tid < 128) {
        int p = tid >> 1, s2 = tid & 1;
        float acc = 0.f;
        #pragma unroll 8
        for (int q = 0; q < 64; q++)
            acc += g_W[p * 64 + q] * (gacc[q][s2] - REG * vs[q][s2]);
        out[b * 256 + 128 + tid] = vs[p][s2] + acc;
    }
}

// ---------------------------------------------------------------------------
extern "C" void kernel_launch(void* const* d_in, const int* in_sizes, int n_in,
                              void* d_out, int out_size) {
    const float* x    = (const float*)d_in[0];
    const float* v    = (const float*)d_in[1];
    const int*   cld  = (const int*)  d_in[2];
    const float* dist = (const float*)d_in[3];
    const float* mu   = (const float*)d_in[4];
    const float* cor  = (const float*)d_in[5];
    const float* Minv = (const float*)d_in[6];
    float* out = (float*)d_out;

    int bs = out_size / 256;

    static const size_t smem_bytes = 128 * 129 * sizeof(float);  // 66048 B
    cudaFuncSetAttribute(solve_batch_kernel,
                         cudaFuncAttributeMaxDynamicSharedMemorySize,
                         (int)smem_bytes);

    prep_W_kernel<<<1, 256>>>(Minv);
    solve_batch_kernel<<<bs, 256, smem_bytes>>>(x, v, cld, dist, mu, cor, out);
}

// round 4
// speedup vs baseline: 1.3063x; 1.3063x over previous
#include <cuda_runtime.h>

// Problem constants (from reference): bs=1024, n=64, d=2, nc=32
#define NPART 64
#define ND    128          // n*d
#define NC    32
#define M4    128          // 4*nc
#define NROW  96           // 3*nc active G rows
#define REG   1e-3f
#define STR   132          // padded row stride (floats): 128 cols + rhs + 3 pad

// Precomputed W = (Minv^{-1} + reg I)^{-1} = (I + reg*Minv)^{-1} Minv  (64x64)
__device__ float g_W[NPART * NPART];

// ---------------------------------------------------------------------------
// Kernel A: W via 4-term Neumann/Horner series (reg*||Minv|| ~ 5e-3, so the
// truncation error is ~(5e-3)^4 ~ 7e-10 relative — far below tolerance).
//   T = I - rM(I - rM(I - rM));  W = M T
// Fully parallel: no serial Gauss-Jordan dependency chain.
// ---------------------------------------------------------------------------
__global__ void prep_W_kernel(const float* __restrict__ Minv) {
    __shared__ float sA[64][64];
    __shared__ float sB[64][64];
    int tid = threadIdx.x;

    // T1 = I - reg*M
    for (int idx = tid; idx < 64 * 64; idx += 256) {
        int r = idx >> 6, c = idx & 63;
        sA[r][c] = ((r == c) ? 1.f : 0.f) - REG * Minv[idx];
    }
    __syncthreads();

    // T2 = I - reg*M@T1 ; T3 = I - reg*M@T2
    for (int it = 0; it < 2; it++) {
        float (*src)[64] = (it == 0) ? sA : sB;
        float (*dst)[64] = (it == 0) ? sB : sA;
        for (int idx = tid; idx < 64 * 64; idx += 256) {
            int r = idx >> 6, c = idx & 63;
            float acc = 0.f;
            #pragma unroll 8
            for (int b = 0; b < 64; b++) acc += Minv[r * 64 + b] * src[b][c];
            dst[r][c] = ((r == c) ? 1.f : 0.f) - REG * acc;
        }
        __syncthreads();
    }

    // W = M @ T3   (T3 in sA)
    for (int idx = tid; idx < 64 * 64; idx += 256) {
        int r = idx >> 6, c = idx & 63;
        float acc = 0.f;
        #pragma unroll 8
        for (int b = 0; b < 64; b++) acc += Minv[r * 64 + b] * sA[b][c];
        g_W[idx] = acc;
    }
}

// ---------------------------------------------------------------------------
// Kernel B: one CTA (256 threads) per batch element.
// Schur complement S (128x128 + rhs col 128) in smem; LU with partial
// pivoting via a row PERMUTATION (no physical swaps), float4-vectorized
// elimination with the pivot search for column k+1 FUSED into step k's
// update (packed u64 argmax + shared atomicMax). 2 barriers per step.
// ---------------------------------------------------------------------------
__global__ void __launch_bounds__(256)
solve_batch_kernel(const float* __restrict__ x, const float* __restrict__ v,
                   const int* __restrict__ cld, const float* __restrict__ dist,
                   const float* __restrict__ mu, const float* __restrict__ cor,
                   float* __restrict__ out) {
    extern __shared__ float S[];          // 128 * 132 floats = 67584 B

    __shared__ float kappa[NC][NC];       // reused as gacc after build
    __shared__ float en[NC][2], et[NC][2];
    __shared__ int   ii[NC], jj[NC];
    __shared__ float hs[NC], mus[NC];
    __shared__ float vs[NPART][2];
    __shared__ float ys[NPART][2];        // reused as sol after rhs build
    __shared__ int   perm[M4];
    __shared__ unsigned long long pivmax;

    float* sol  = &ys[0][0];
    float* gacc = &kappa[0][0];

    const int b    = blockIdx.x;
    const int tid  = threadIdx.x;
    const int r    = tid & 127;
    const int half = tid >> 7;
    const float* xb = x + b * ND;
    const float* vb = v + b * ND;

    // ---- load + per-contact geometry -------------------------------------
    if (tid < 128) {
        out[b * 256 + tid] = xb[tid];            // x passes through unchanged
        vs[tid >> 1][tid & 1] = vb[tid];
    }
    if (tid == 0) pivmax = 0ULL;
    if (tid < NC) {
        int c = tid;
        int i = cld[b * (NC * 2) + c * 2 + 0];
        int j = cld[b * (NC * 2) + c * 2 + 1];
        ii[c] = i; jj[c] = j;
        float dx = xb[j * 2 + 0] - xb[i * 2 + 0];
        float dy = xb[j * 2 + 1] - xb[i * 2 + 1];
        float inv = rsqrtf(dx * dx + dy * dy);
        float ex = dx * inv, ey = dy * inv;
        en[c][0] = ex;  en[c][1] = ey;
        et[c][0] = -ey; et[c][1] = ex;
        float jv = ex * (vb[j * 2] - vb[i * 2]) + ey * (vb[j * 2 + 1] - vb[i * 2 + 1]);
        hs[c]  = fminf(dist[b * NC + c] * 12.5f, cor[b * NC + c] * jv);  // dist/(DT*8)
        mus[c] = mu[b * NC + c];
    }
    __syncthreads();

    // ---- kappa[cr][cs] = W[ii,is] - W[ii,js] - W[ji,is] + W[ji,js] --------
    for (int idx = tid; idx < NC * NC; idx += 256) {
        int cr = idx >> 5, cs = idx & 31;
        int ir = ii[cr], jr = jj[cr], is = ii[cs], js = jj[cs];
        kappa[cr][cs] = g_W[ir * 64 + is] - g_W[ir * 64 + js]
                      - g_W[jr * 64 + is] + g_W[jr * 64 + js];
    }

    // ---- y = A^{-1} r1 = -v + reg * (W v) ---------------------------------
    if (tid < 128) {
        int p = tid >> 1, s2 = tid & 1;
        float acc = 0.f;
        #pragma unroll 8
        for (int q = 0; q < 64; q++) acc += g_W[p * 64 + q] * vs[q][s2];
        ys[p][s2] = -vs[p][s2] + REG * acc;
    }
    __syncthreads();

    // ---- build S = D - G A^{-1} G^T + reg I, rhs at col 128 ---------------
    // thread covers row r, columns c = half, half+2, ...  (col 0 -> half 0)
    unsigned long long key0 = 0;
    {
        float* Sr = S + r * STR;
        // row-r direction factors (precompute outside column loop)
        int cr; float drx, dry;
        if (r < NC) { cr = r; drx = en[r][0]; dry = en[r][1]; }
        else if (r < NROW) {
            int q = (r - NC) >> 1; cr = q;
            float sg = ((r - NC) & 1) ? -1.f : 1.f;
            drx = sg * et[q][0]; dry = sg * et[q][1];
        } else { cr = -1; drx = 0.f; dry = 0.f; }

        for (int c = half; c < STR; c += 2) {
            float val;
            if (c < 128) {
                int s = c;
                if (r < NROW && s < NROW) {
                    int cs; float dsx, dsy;
                    if (s < NC) { cs = s; dsx = en[s][0]; dsy = en[s][1]; }
                    else { int q = (s - NC) >> 1; cs = q;
                           float sg = ((s - NC) & 1) ? -1.f : 1.f;
                           dsx = sg * et[q][0]; dsy = sg * et[q][1]; }
                    val = -(drx * dsx + dry * dsy) * kappa[cr][cs];
                    if (r == s) val += REG;
                } else if (r < NC) {
                    val = 0.f;
                } else if (r < NROW) {
                    int q = (r - NC) >> 1;                        // -E block
                    val = (q == s - NROW) ? -1.f : 0.f;
                } else {
                    int q = r - NROW;
                    if (s < NC)        val = (s == q) ? -mus[q] : 0.f;
                    else if (s < NROW) val = (((s - NC) >> 1) == q) ? 1.f : 0.f;
                    else               val = (s - NROW == q) ? REG : 0.f;
                }
            } else if (c == 128) {
                // rhs = -h - d_r . (y_j - y_i)
                val = 0.f;
                if (r < NC) {
                    float dx = ys[jj[r]][0] - ys[ii[r]][0];
                    float dy = ys[jj[r]][1] - ys[ii[r]][1];
                    val = -hs[r] - (en[r][0] * dx + en[r][1] * dy);
                } else if (r < NROW) {
                    float dx = ys[jj[cr]][0] - ys[ii[cr]][0];
                    float dy = ys[jj[cr]][1] - ys[ii[cr]][1];
                    val = -(drx * dx + dry * dy);
                }
            } else {
                val = 0.f;                                        // pad cols
            }
            Sr[c] = val;
            if (c == 0)
                key0 = (((unsigned long long)__float_as_uint(fabsf(val))) << 32)
                     | (unsigned)r;
        }
    }
    // fused argmax for pivot column 0
    if (half == 0) {
        #pragma unroll
        for (int off = 16; off; off >>= 1) {
            unsigned long long o = __shfl_down_sync(0xffffffffu, key0, off);
            if (o > key0) key0 = o;
        }
        if ((tid & 31) == 0) atomicMax(&pivmax, key0);
    }

    // ---- LU with permutation pivoting, vectorized elimination -------------
    bool active = true;
    for (int k = 0; k < M4; k++) {
        __syncthreads();                           // (A) atomics + writes done
        if (tid == 0) {
            unsigned long long mv = pivmax;
            pivmax = 0ULL;
            perm[k] = (int)(mv & 0xffffffffULL);
        }
        __syncthreads();                           // (B)
        int pr = perm[k];
        if (r == pr) active = false;

        int c1 = (k + 1) >> 2;
        int e1 = (k + 1) & 3;
        bool owner = ((c1 & 1) == half);
        unsigned long long key = 0;

        if (active) {
            const float* Pr = S + pr * STR;
            float*       Sr = S + r  * STR;
            float m = Sr[k] / Pr[k];
            int c = owner ? c1 : c1 + 1;
            if (owner) {
                // first chunk: masked merge (cols <= k written back unchanged
                // -> benign bit-identical race with the partner's m-read)
                float4 p = *(const float4*)(Pr + 4 * c1);
                float4 o = *(const float4*)(Sr + 4 * c1);
                float4 u;
                u.x = o.x - m * p.x; u.y = o.y - m * p.y;
                u.z = o.z - m * p.z; u.w = o.w - m * p.w;
                if (e1 > 0) u.x = o.x;
                if (e1 > 1) u.y = o.y;
                if (e1 > 2) u.z = o.z;
                *(float4*)(Sr + 4 * c1) = u;
                float cand = (e1 == 0) ? u.x : (e1 == 1) ? u.y
                           : (e1 == 2) ? u.z : u.w;
                key = (((unsigned long long)__float_as_uint(fabsf(cand))) << 32)
                    | (unsigned)r;
                c += 2;
            }
            #pragma unroll 2
            for (; c <= 32; c += 2) {
                float4 p = *(const float4*)(Pr + 4 * c);
                float4 o = *(const float4*)(Sr + 4 * c);
                o.x -= m * p.x; o.y -= m * p.y;
                o.z -= m * p.z; o.w -= m * p.w;
                *(float4*)(Sr + 4 * c) = o;
            }
        }
        if (owner) {                               // uniform per warp
            #pragma unroll
            for (int off = 16; off; off >>= 1) {
                unsigned long long o = __shfl_down_sync(0xffffffffu, key, off);
                if (o > key) key = o;
            }
            if ((tid & 31) == 0 && key) atomicMax(&pivmax, key);
        }
    }
    __syncthreads();

    // ---- back substitution (warp 0, no block barriers) ---------------------
    if (tid < 32) {
        int p0 = perm[tid],      p1 = perm[tid + 32];
        int p2 = perm[tid + 64], p3 = perm[tid + 96];
        for (int k = M4 - 1; k >= 0; k--) {
            int q = k >> 5, src = k & 31;
            int pk = (q == 0) ? p0 : (q == 1) ? p1 : (q == 2) ? p2 : p3;
            float cand = S[pk * STR + 128] / S[pk * STR + k];
            float lk = __shfl_sync(0xffffffffu, cand, src);
            if (tid == src) sol[k] = lk;
            if (tid      < k) S[p0 * STR + 128] -= S[p0 * STR + k] * lk;
            if (tid + 32 < k) S[p1 * STR + 128] -= S[p1 * STR + k] * lk;
            if (tid + 64 < k) S[p2 * STR + 128] -= S[p2 * STR + k] * lk;
            if (tid + 96 < k) S[p3 * STR + 128] -= S[p3 * STR + k] * lk;
            __syncwarp();
        }
    }
    __syncthreads();

    // ---- g = G^T l  (sparse scatter, smem atomics) -------------------------
    if (tid < 128) gacc[tid] = 0.f;
    __syncthreads();
    if (tid < NC) {
        int c = tid;
        float wn = sol[c];
        float wt = sol[NC + 2 * c] - sol[NC + 2 * c + 1];
        float wx = wn * en[c][0] + wt * et[c][0];
        float wy = wn * en[c][1] + wt * et[c][1];
        atomicAdd(&gacc[ii[c] * 2 + 0], -wx);
        atomicAdd(&gacc[ii[c] * 2 + 1], -wy);
        atomicAdd(&gacc[jj[c] * 2 + 0],  wx);
        atomicAdd(&gacc[jj[c] * 2 + 1],  wy);
    }
    __syncthreads();

    // ---- v_plus = v + W (g - reg*v) ----------------------------------------
    if (tid < 128) {
        int p = tid >> 1, s2 = tid & 1;
        float acc = 0.f;
        #pragma unroll 8
        for (int q = 0; q < 64; q++)
            acc += g_W[p * 64 + q] * (gacc[q * 2 + s2] - REG * vs[q][s2]);
        out[b * 256 + 128 + tid] = vs[p][s2] + acc;
    }
}

// ---------------------------------------------------------------------------
extern "C" void kernel_launch(void* const* d_in, const int* in_sizes, int n_in,
                              void* d_out, int out_size) {
    const float* x    = (const float*)d_in[0];
    const float* v    = (const float*)d_in[1];
    const int*   cld  = (const int*)  d_in[2];
    const float* dist = (const float*)d_in[3];
    const float* mu   = (const float*)d_in[4];
    const float* cor  = (const float*)d_in[5];
    const float* Minv = (const float*)d_in[6];
    float* out = (float*)d_out;

    int bs = out_size / 256;

    const size_t smem_bytes = M4 * STR * sizeof(float);  // 67584 B
    cudaFuncSetAttribute(solve_batch_kernel,
                         cudaFuncAttributeMaxDynamicSharedMemorySize,
                         (int)smem_bytes);

    prep_W_kernel<<<1, 256>>>(Minv);
    solve_batch_kernel<<<bs, 256, smem_bytes>>>(x, v, cld, dist, mu, cor, out);
}

// round 5
// speedup vs baseline: 1.5579x; 1.1926x over previous
#include <cuda_runtime.h>

// Problem constants (from reference): bs=1024, n=64, d=2, nc=32
#define NPART 64
#define ND    128          // n*d
#define NC    32
#define M4    128          // 4*nc
#define NROW  96           // 3*nc active G rows
#define REG   1e-3f
#define STR   132          // padded row stride (floats): 128 cols + rhs + 3 pad

// Precomputed W = (Minv^{-1} + reg I)^{-1} = (I + reg*Minv)^{-1} Minv  (64x64)
__device__ float g_W[NPART * NPART];

static __device__ __forceinline__ unsigned long long packkey(float v, int r) {
    return (((unsigned long long)__float_as_uint(fabsf(v))) << 32) | (unsigned)r;
}

// ---------------------------------------------------------------------------
// Kernel A: W via 4-term Neumann/Horner series (reg*||Minv|| ~ 5e-3 ->
// truncation ~7e-10 relative). Fully parallel, no serial GJ chain.
// ---------------------------------------------------------------------------
__global__ void prep_W_kernel(const float* __restrict__ Minv) {
    __shared__ float sA[64][64];
    __shared__ float sB[64][64];
    int tid = threadIdx.x;

    for (int idx = tid; idx < 64 * 64; idx += 256) {
        int r = idx >> 6, c = idx & 63;
        sA[r][c] = ((r == c) ? 1.f : 0.f) - REG * Minv[idx];
    }
    __syncthreads();

    for (int it = 0; it < 2; it++) {
        float (*src)[64] = (it == 0) ? sA : sB;
        float (*dst)[64] = (it == 0) ? sB : sA;
        for (int idx = tid; idx < 64 * 64; idx += 256) {
            int r = idx >> 6, c = idx & 63;
            float acc = 0.f;
            #pragma unroll 8
            for (int b = 0; b < 64; b++) acc += Minv[r * 64 + b] * src[b][c];
            dst[r][c] = ((r == c) ? 1.f : 0.f) - REG * acc;
        }
        __syncthreads();
    }

    for (int idx = tid; idx < 64 * 64; idx += 256) {
        int r = idx >> 6, c = idx & 63;
        float acc = 0.f;
        #pragma unroll 8
        for (int b = 0; b < 64; b++) acc += Minv[r * 64 + b] * sA[b][c];
        g_W[idx] = acc;
    }
}

// ---------------------------------------------------------------------------
// Kernel B: one CTA (256 threads) per batch element. Schur complement S in
// smem; BLOCKED LU (panel width 4) with permutation pivoting. Trailing matrix
// sees one rank-4 float4 update per panel (4x less smem traffic than rank-1),
// pivot argmax for the next column is fused into each update pass.
// ---------------------------------------------------------------------------
__global__ void __launch_bounds__(256)
solve_batch_kernel(const float* __restrict__ x, const float* __restrict__ v,
                   const int* __restrict__ cld, const float* __restrict__ dist,
                   const float* __restrict__ mu, const float* __restrict__ cor,
                   float* __restrict__ out) {
    extern __shared__ float S[];          // 128 * 132 floats = 67584 B

    __shared__ float kappa[NC][NC];       // reused as gacc after build
    __shared__ float en[NC][2], et[NC][2];
    __shared__ int   ii[NC], jj[NC];
    __shared__ float hs[NC], mus[NC];
    __shared__ float vs[NPART][2];
    __shared__ float ys[NPART][2];        // reused as sol after rhs build
    __shared__ int   perm[M4];
    __shared__ unsigned long long pivmax;
    __shared__ float s_pinv;
    __shared__ float coef[6];             // c10,c20,c21,c30,c31,c32

    float* sol  = &ys[0][0];
    float* gacc = &kappa[0][0];

    const int b    = blockIdx.x;
    const int tid  = threadIdx.x;
    const int r    = tid & 127;
    const int half = tid >> 7;
    const float* xb = x + b * ND;
    const float* vb = v + b * ND;

    // ---- load + per-contact geometry -------------------------------------
    if (tid < 128) {
        out[b * 256 + tid] = xb[tid];            // x passes through unchanged
        vs[tid >> 1][tid & 1] = vb[tid];
    }
    if (tid == 0) pivmax = 0ULL;
    if (tid < NC) {
        int c = tid;
        int i = cld[b * (NC * 2) + c * 2 + 0];
        int j = cld[b * (NC * 2) + c * 2 + 1];
        ii[c] = i; jj[c] = j;
        float dx = xb[j * 2 + 0] - xb[i * 2 + 0];
        float dy = xb[j * 2 + 1] - xb[i * 2 + 1];
        float inv = rsqrtf(dx * dx + dy * dy);
        float ex = dx * inv, ey = dy * inv;
        en[c][0] = ex;  en[c][1] = ey;
        et[c][0] = -ey; et[c][1] = ex;
        float jv = ex * (vb[j * 2] - vb[i * 2]) + ey * (vb[j * 2 + 1] - vb[i * 2 + 1]);
        hs[c]  = fminf(dist[b * NC + c] * 12.5f, cor[b * NC + c] * jv);  // dist/(DT*8)
        mus[c] = mu[b * NC + c];
    }
    __syncthreads();

    // ---- kappa[cr][cs] = W[ii,is] - W[ii,js] - W[ji,is] + W[ji,js] --------
    for (int idx = tid; idx < NC * NC; idx += 256) {
        int cr = idx >> 5, cs = idx & 31;
        int ir = ii[cr], jr = jj[cr], is = ii[cs], js = jj[cs];
        kappa[cr][cs] = g_W[ir * 64 + is] - g_W[ir * 64 + js]
                      - g_W[jr * 64 + is] + g_W[jr * 64 + js];
    }

    // ---- y = A^{-1} r1 = -v + reg * (W v) ---------------------------------
    if (tid < 128) {
        int p = tid >> 1, s2 = tid & 1;
        float acc = 0.f;
        #pragma unroll 8
        for (int q = 0; q < 64; q++) acc += g_W[p * 64 + q] * vs[q][s2];
        ys[p][s2] = -vs[p][s2] + REG * acc;
    }
    __syncthreads();

    // ---- build S = D - G A^{-1} G^T + reg I, rhs at col 128 ---------------
    unsigned long long key0 = 0;
    {
        float* Sr = S + r * STR;
        int cr; float drx, dry;
        if (r < NC) { cr = r; drx = en[r][0]; dry = en[r][1]; }
        else if (r < NROW) {
            int q = (r - NC) >> 1; cr = q;
            float sg = ((r - NC) & 1) ? -1.f : 1.f;
            drx = sg * et[q][0]; dry = sg * et[q][1];
        } else { cr = -1; drx = 0.f; dry = 0.f; }

        for (int c = half; c < STR; c += 2) {
            float val;
            if (c < 128) {
                int s = c;
                if (r < NROW && s < NROW) {
                    int cs; float dsx, dsy;
                    if (s < NC) { cs = s; dsx = en[s][0]; dsy = en[s][1]; }
                    else { int q = (s - NC) >> 1; cs = q;
                           float sg = ((s - NC) & 1) ? -1.f : 1.f;
                           dsx = sg * et[q][0]; dsy = sg * et[q][1]; }
                    val = -(drx * dsx + dry * dsy) * kappa[cr][cs];
                    if (r == s) val += REG;
                } else if (r < NC) {
                    val = 0.f;
                } else if (r < NROW) {
                    int q = (r - NC) >> 1;                        // -E block
                    val = (q == s - NROW) ? -1.f : 0.f;
                } else {
                    int q = r - NROW;
                    if (s < NC)        val = (s == q) ? -mus[q] : 0.f;
                    else if (s < NROW) val = (((s - NC) >> 1) == q) ? 1.f : 0.f;
                    else               val = (s - NROW == q) ? REG : 0.f;
                }
            } else if (c == 128) {
                val = 0.f;
                if (r < NC) {
                    float dx = ys[jj[r]][0] - ys[ii[r]][0];
                    float dy = ys[jj[r]][1] - ys[ii[r]][1];
                    val = -hs[r] - (en[r][0] * dx + en[r][1] * dy);
                } else if (r < NROW) {
                    float dx = ys[jj[cr]][0] - ys[ii[cr]][0];
                    float dy = ys[jj[cr]][1] - ys[ii[cr]][1];
                    val = -(drx * dx + dry * dy);
                }
            } else {
                val = 0.f;                                        // pad cols
            }
            Sr[c] = val;
            if (c == 0) key0 = packkey(val, r);
        }
    }
    if (half == 0) {                     // fused argmax for pivot column 0
        #pragma unroll
        for (int off = 16; off; off >>= 1) {
            unsigned long long o = __shfl_down_sync(0xffffffffu, key0, off);
            if (o > key0) key0 = o;
        }
        if ((tid & 31) == 0) atomicMax(&pivmax, key0);
    }

    // ---- blocked LU, panel width 4, permutation pivoting -------------------
    bool active = true;
    for (int k0 = 0; k0 < M4; k0 += 4) {
        // ================= Phase A: panel factorization ====================
        #pragma unroll
        for (int t = 0; t < 4; t++) {
            const int k = k0 + t;
            __syncthreads();                       // prior writes/atomics done
            if (tid == 0) {
                unsigned long long mv = pivmax;
                pivmax = 0ULL;
                int p = (int)(mv & 0xffffffffULL);
                perm[k] = p;
                s_pinv = 1.f / S[p * STR + k];
            }
            __syncthreads();
            const int pr = perm[k];
            if (r == pr) active = false;
            if (half == 0) {
                float m = 0.f;
                if (active) {
                    m = S[r * STR + k] * s_pinv;
                    S[r * STR + k] = m;            // store multiplier (L)
                }
                unsigned long long mykey = 0;
                #pragma unroll
                for (int c = k + 1; c < k0 + 4; c++) {
                    if (active) {
                        float u = S[r * STR + c] - m * S[pr * STR + c];
                        S[r * STR + c] = u;
                        if (c == k + 1) mykey = packkey(u, r);
                    }
                }
                if (t < 3) {
                    #pragma unroll
                    for (int off = 16; off; off >>= 1) {
                        unsigned long long o = __shfl_down_sync(0xffffffffu, mykey, off);
                        if (o > mykey) mykey = o;
                    }
                    if ((tid & 31) == 0 && mykey) atomicMax(&pivmax, mykey);
                }
            }
        }

        // ================= Phase B: update the 4 pivot rows ================
        const int cstart = (k0 >> 2) + 1;          // first trailing chunk
        const int nch    = 33 - cstart;            // trailing chunks (incl rhs)
        __syncthreads();                           // multipliers all stored
        if (tid == 0) {
            const float* R1 = S + perm[k0 + 1] * STR;
            const float* R2 = S + perm[k0 + 2] * STR;
            const float* R3 = S + perm[k0 + 3] * STR;
            float m10 = R1[k0];
            float m20 = R2[k0], m21 = R2[k0 + 1];
            float m30 = R3[k0], m31 = R3[k0 + 1], m32 = R3[k0 + 2];
            float c10 = -m10;
            float c21 = -m21;
            float c20 = -m20 + m21 * m10;
            float c32 = -m32;
            float c31 = -m31 + m32 * m21;
            float c30 = -m30 + m31 * m10 - m32 * c20;
            coef[0] = c10; coef[1] = c20; coef[2] = c21;
            coef[3] = c30; coef[4] = c31; coef[5] = c32;
        }
        // read-all / sync / write-all so P1,P2 originals aren't clobbered early
        float4 q0, q1, q2, q3;
        int jrow = 0, cc = 0;
        if (tid < 3 * nch) {
            jrow = 1 + tid / nch;
            cc   = cstart + tid % nch;
            q0 = *(const float4*)(S + perm[k0 + 0] * STR + 4 * cc);
            q1 = *(const float4*)(S + perm[k0 + 1] * STR + 4 * cc);
            q2 = *(const float4*)(S + perm[k0 + 2] * STR + 4 * cc);
            q3 = *(const float4*)(S + perm[k0 + 3] * STR + 4 * cc);
        }
        __syncthreads();                           // reads + coefs done
        if (tid < 3 * nch) {
            float4 o;
            if (jrow == 1) {
                o.x = q1.x + coef[0] * q0.x; o.y = q1.y + coef[0] * q0.y;
                o.z = q1.z + coef[0] * q0.z; o.w = q1.w + coef[0] * q0.w;
            } else if (jrow == 2) {
                o.x = q2.x + coef[2] * q1.x + coef[1] * q0.x;
                o.y = q2.y + coef[2] * q1.y + coef[1] * q0.y;
                o.z = q2.z + coef[2] * q1.z + coef[1] * q0.z;
                o.w = q2.w + coef[2] * q1.w + coef[1] * q0.w;
            } else {
                o.x = q3.x + coef[5] * q2.x + coef[4] * q1.x + coef[3] * q0.x;
                o.y = q3.y + coef[5] * q2.y + coef[4] * q1.y + coef[3] * q0.y;
                o.z = q3.z + coef[5] * q2.z + coef[4] * q1.z + coef[3] * q0.z;
                o.w = q3.w + coef[5] * q2.w + coef[4] * q1.w + coef[3] * q0.w;
            }
            *(float4*)(S + perm[k0 + jrow] * STR + 4 * cc) = o;
        }
        __syncthreads();                           // pivot rows final

        // ================= Phase C: rank-4 trailing update =================
        unsigned long long key = 0;
        if (active) {
            float* Sr = S + r * STR;
            const float m0 = Sr[k0 + 0];
            const float m1 = Sr[k0 + 1];
            const float m2 = Sr[k0 + 2];
            const float m3 = Sr[k0 + 3];
            const float* P0 = S + perm[k0 + 0] * STR;
            const float* P1 = S + perm[k0 + 1] * STR;
            const float* P2 = S + perm[k0 + 2] * STR;
            const float* P3 = S + perm[k0 + 3] * STR;
            const bool firstowner = ((cstart & 1) == half);
            for (int c = cstart + (firstowner ? 0 : 1); c <= 32; c += 2) {
                float4 s  = *(const float4*)(Sr + 4 * c);
                float4 p0 = *(const float4*)(P0 + 4 * c);
                float4 p1 = *(const float4*)(P1 + 4 * c);
                float4 p2 = *(const float4*)(P2 + 4 * c);
                float4 p3 = *(const float4*)(P3 + 4 * c);
                s.x -= m0 * p0.x + m1 * p1.x + m2 * p2.x + m3 * p3.x;
                s.y -= m0 * p0.y + m1 * p1.y + m2 * p2.y + m3 * p3.y;
                s.z -= m0 * p0.z + m1 * p1.z + m2 * p2.z + m3 * p3.z;
                s.w -= m0 * p0.w + m1 * p1.w + m2 * p2.w + m3 * p3.w;
                *(float4*)(Sr + 4 * c) = s;
                if (c == cstart) key = packkey(s.x, r);   // column k0+4
            }
        }
        if (k0 + 4 < M4) {                         // feed next panel's pivot
            #pragma unroll
            for (int off = 16; off; off >>= 1) {
                unsigned long long o = __shfl_down_sync(0xffffffffu, key, off);
                if (o > key) key = o;
            }
            if ((tid & 31) == 0 && key) atomicMax(&pivmax, key);
        }
    }
    __syncthreads();

    // ---- back substitution (warp 0, no block barriers) ---------------------
    if (tid < 32) {
        int p0 = perm[tid],      p1 = perm[tid + 32];
        int p2 = perm[tid + 64], p3 = perm[tid + 96];
        for (int k = M4 - 1; k >= 0; k--) {
            int q = k >> 5, src = k & 31;
            int pk = (q == 0) ? p0 : (q == 1) ? p1 : (q == 2) ? p2 : p3;
            float cand = S[pk * STR + 128] / S[pk * STR + k];
            float lk = __shfl_sync(0xffffffffu, cand, src);
            if (tid == src) sol[k] = lk;
            if (tid      < k) S[p0 * STR + 128] -= S[p0 * STR + k] * lk;
            if (tid + 32 < k) S[p1 * STR + 128] -= S[p1 * STR + k] * lk;
            if (tid + 64 < k) S[p2 * STR + 128] -= S[p2 * STR + k] * lk;
            if (tid + 96 < k) S[p3 * STR + 128] -= S[p3 * STR + k] * lk;
            __syncwarp();
        }
    }
    __syncthreads();

    // ---- g = G^T l  (sparse scatter, smem atomics) -------------------------
    if (tid < 128) gacc[tid] = 0.f;
    __syncthreads();
    if (tid < NC) {
        int c = tid;
        float wn = sol[c];
        float wt = sol[NC + 2 * c] - sol[NC + 2 * c + 1];
        float wx = wn * en[c][0] + wt * et[c][0];
        float wy = wn * en[c][1] + wt * et[c][1];
        atomicAdd(&gacc[ii[c] * 2 + 0], -wx);
        atomicAdd(&gacc[ii[c] * 2 + 1], -wy);
        atomicAdd(&gacc[jj[c] * 2 + 0],  wx);
        atomicAdd(&gacc[jj[c] * 2 + 1],  wy);
    }
    __syncthreads();

    // ---- v_plus = v + W (g - reg*v) ----------------------------------------
    if (tid < 128) {
        int p = tid >> 1, s2 = tid & 1;
        float acc = 0.f;
        #pragma unroll 8
        for (int q = 0; q < 64; q++)
            acc += g_W[p * 64 + q] * (gacc[q * 2 + s2] - REG * vs[q][s2]);
        out[b * 256 + 128 + tid] = vs[p][s2] + acc;
    }
}

// ---------------------------------------------------------------------------
extern "C" void kernel_launch(void* const* d_in, const int* in_sizes, int n_in,
                              void* d_out, int out_size) {
    const float* x    = (const float*)d_in[0];
    const float* v    = (const float*)d_in[1];
    const int*   cld  = (const int*)  d_in[2];
    const float* dist = (const float*)d_in[3];
    const float* mu   = (const float*)d_in[4];
    const float* cor  = (const float*)d_in[5];
    const float* Minv = (const float*)d_in[6];
    float* out = (float*)d_out;

    int bs = out_size / 256;

    const size_t smem_bytes = M4 * STR * sizeof(float);  // 67584 B
    cudaFuncSetAttribute(solve_batch_kernel,
                         cudaFuncAttributeMaxDynamicSharedMemorySize,
                         (int)smem_bytes);

    prep_W_kernel<<<1, 256>>>(Minv);
    solve_batch_kernel<<<bs, 256, smem_bytes>>>(x, v, cld, dist, mu, cor, out);
}

// round 7
// speedup vs baseline: 1.9636x; 1.2604x over previous
#include <cuda_runtime.h>

// Problem constants (from reference): bs=1024, n=64, d=2, nc=32
#define NPART 64
#define ND    128          // n*d
#define NC    32
#define M4    128          // 4*nc
#define NROW  96           // 3*nc active G rows
#define REG   1e-3f
#define STR   132          // padded row stride (floats): 128 cols + rhs + 3 pad

// Precomputed W = (Minv^{-1} + reg I)^{-1} = (I + reg*Minv)^{-1} Minv  (64x64)
__device__ float g_W[NPART * NPART];
__device__ float g_T1[NPART * NPART];
__device__ float g_T2[NPART * NPART];

static __device__ __forceinline__ unsigned long long packkey(float v, int r) {
    return (((unsigned long long)__float_as_uint(fabsf(v))) << 32) | (unsigned)r;
}

// ---------------------------------------------------------------------------
// Prep: W via 4-term Neumann/Horner series (reg*||Minv|| ~ 5e-3 ->
// truncation ~7e-10). Column-parallel across 16 CTAs per step.
// NOTE: device globals are referenced in DEVICE code only (mode-selected);
// passing __device__ symbols as host-side kernel args binds the host shadow
// variable (silently GPU-accessible via ATS on GB300) — that was the R5 bug.
// ---------------------------------------------------------------------------
__global__ void prep_T1_kernel(const float* __restrict__ Minv) {
    int idx = blockIdx.x * 256 + threadIdx.x;
    int r = idx >> 6, c = idx & 63;
    g_T1[idx] = ((r == c) ? 1.f : 0.f) - REG * Minv[idx];
}

// mode 0: g_T2 = I - reg*M@g_T1
// mode 1: g_T1 = I - reg*M@g_T2
// mode 2: g_W  =         M@g_T1
__global__ void prep_mm_kernel(const float* __restrict__ Minv, int mode) {
    int idx = blockIdx.x * 256 + threadIdx.x;
    int r = idx >> 6, c = idx & 63;
    const float* src = (mode == 1) ? g_T2 : g_T1;
    float acc = 0.f;
    #pragma unroll 8
    for (int b = 0; b < 64; b++) acc += Minv[r * 64 + b] * src[b * 64 + c];
    if (mode == 0)      g_T2[idx] = ((r == c) ? 1.f : 0.f) - REG * acc;
    else if (mode == 1) g_T1[idx] = ((r == c) ? 1.f : 0.f) - REG * acc;
    else                g_W[idx]  = acc;
}

// ---------------------------------------------------------------------------
// Kernel B: one CTA (256 threads) per batch element. Schur complement S in
// smem; blocked LU (panel 4) with permutation pivoting. The panel is
// factorized ENTIRELY IN REGISTERS by warp 0 (shuffle argmax + broadcast, no
// block barriers, no atomics), and the pivot-row correction is folded into
// the rank-4 trailing update via composed coefficients. 3 barriers/panel.
// ---------------------------------------------------------------------------
__global__ void __launch_bounds__(256)
solve_batch_kernel(const float* __restrict__ x, const float* __restrict__ v,
                   const int* __restrict__ cld, const float* __restrict__ dist,
                   const float* __restrict__ mu, const float* __restrict__ cor,
                   float* __restrict__ out) {
    extern __shared__ float S[];          // 128 * 132 floats = 67584 B

    __shared__ float kappa[NC][NC];       // reused: pivot-row scratch, then gacc
    __shared__ float en[NC][2], et[NC][2];
    __shared__ int   ii[NC], jj[NC];
    __shared__ float hs[NC], mus[NC];
    __shared__ float vs[NPART][2];
    __shared__ float ys[NPART][2];        // reused as sol
    __shared__ int   perm[M4];
    __shared__ float coef[6];             // c10,c20,c21,c30,c31,c32

    float* sol     = &ys[0][0];
    float* gacc    = &kappa[0][0];
    float* scratch = &kappa[0][0];        // 4 x 132 floats = 2112 B (< 4 KB)

    const int b    = blockIdx.x;
    const int tid  = threadIdx.x;
    const int r    = tid & 127;
    const int half = tid >> 7;
    const float* xb = x + b * ND;
    const float* vb = v + b * ND;

    // ---- load + per-contact geometry -------------------------------------
    if (tid < 128) {
        out[b * 256 + tid] = xb[tid];            // x passes through unchanged
        vs[tid >> 1][tid & 1] = vb[tid];
    }
    if (tid < NC) {
        int c = tid;
        int i = cld[b * (NC * 2) + c * 2 + 0];
        int j = cld[b * (NC * 2) + c * 2 + 1];
        ii[c] = i; jj[c] = j;
        float dx = xb[j * 2 + 0] - xb[i * 2 + 0];
        float dy = xb[j * 2 + 1] - xb[i * 2 + 1];
        float inv = rsqrtf(dx * dx + dy * dy);
        float ex = dx * inv, ey = dy * inv;
        en[c][0] = ex;  en[c][1] = ey;
        et[c][0] = -ey; et[c][1] = ex;
        float jv = ex * (vb[j * 2] - vb[i * 2]) + ey * (vb[j * 2 + 1] - vb[i * 2 + 1]);
        hs[c]  = fminf(dist[b * NC + c] * 12.5f, cor[b * NC + c] * jv);  // dist/(DT*8)
        mus[c] = mu[b * NC + c];
    }
    __syncthreads();

    // ---- kappa[cr][cs] = W[ii,is] - W[ii,js] - W[ji,is] + W[ji,js] --------
    for (int idx = tid; idx < NC * NC; idx += 256) {
        int cr = idx >> 5, cs = idx & 31;
        int ir = ii[cr], jr = jj[cr], is = ii[cs], js = jj[cs];
        kappa[cr][cs] = g_W[ir * 64 + is] - g_W[ir * 64 + js]
                      - g_W[jr * 64 + is] + g_W[jr * 64 + js];
    }

    // ---- y = A^{-1} r1 = -v + reg * (W v) ---------------------------------
    if (tid < 128) {
        int p = tid >> 1, s2 = tid & 1;
        float acc = 0.f;
        #pragma unroll 8
        for (int q = 0; q < 64; q++) acc += g_W[p * 64 + q] * vs[q][s2];
        ys[p][s2] = -vs[p][s2] + REG * acc;
    }
    __syncthreads();

    // ---- build S = D - G A^{-1} G^T + reg I, rhs at col 128 ---------------
    {
        float* Sr = S + r * STR;
        int cr; float drx, dry;
        if (r < NC) { cr = r; drx = en[r][0]; dry = en[r][1]; }
        else if (r < NROW) {
            int q = (r - NC) >> 1; cr = q;
            float sg = ((r - NC) & 1) ? -1.f : 1.f;
            drx = sg * et[q][0]; dry = sg * et[q][1];
        } else { cr = -1; drx = 0.f; dry = 0.f; }

        for (int c = half; c < STR; c += 2) {
            float val;
            if (c < 128) {
                int s = c;
                if (r < NROW && s < NROW) {
                    int cs; float dsx, dsy;
                    if (s < NC) { cs = s; dsx = en[s][0]; dsy = en[s][1]; }
                    else { int q = (s - NC) >> 1; cs = q;
                           float sg = ((s - NC) & 1) ? -1.f : 1.f;
                           dsx = sg * et[q][0]; dsy = sg * et[q][1]; }
                    val = -(drx * dsx + dry * dsy) * kappa[cr][cs];
                    if (r == s) val += REG;
                } else if (r < NC) {
                    val = 0.f;
                } else if (r < NROW) {
                    int q = (r - NC) >> 1;                        // -E block
                    val = (q == s - NROW) ? -1.f : 0.f;
                } else {
                    int q = r - NROW;
                    if (s < NC)        val = (s == q) ? -mus[q] : 0.f;
                    else if (s < NROW) val = (((s - NC) >> 1) == q) ? 1.f : 0.f;
                    else               val = (s - NROW == q) ? REG : 0.f;
                }
            } else if (c == 128) {
                val = 0.f;
                if (r < NC) {
                    float dx = ys[jj[r]][0] - ys[ii[r]][0];
                    float dy = ys[jj[r]][1] - ys[ii[r]][1];
                    val = -hs[r] - (en[r][0] * dx + en[r][1] * dy);
                } else if (r < NROW) {
                    float dx = ys[jj[cr]][0] - ys[ii[cr]][0];
                    float dy = ys[jj[cr]][1] - ys[ii[cr]][1];
                    val = -(drx * dx + dry * dy);
                }
            } else {
                val = 0.f;                                        // pad cols
            }
            Sr[c] = val;
        }
    }

    // ---- blocked LU: in-register panel + unified rank-4 update -------------
    bool rowactive = true;     // per (r,half) thread; row not yet pivoted
    unsigned fz = 0;           // warp 0 only: frozen mask for its 4 rows

    for (int k0 = 0; k0 < M4; k0 += 4) {
        __syncthreads();       // (1) previous trailing update / build complete

        // ===== panel factorization, warp 0, registers only =================
        if (tid < 32) {
            const int lane = tid;
            float4 pv[4];
            #pragma unroll
            for (int i = 0; i < 4; i++)
                pv[i] = *(const float4*)(S + (lane + 32 * i) * STR + k0);

            int   prows[4];
            float4 tsel;   // pivot-owner's selected row (valid on owner lane)

            #pragma unroll
            for (int t = 0; t < 4; t++) {
                // ---- argmax over non-frozen rows (|col t| value) ----
                unsigned long long key = 0;
                #pragma unroll
                for (int i = 0; i < 4; i++) {
                    float cand = (t == 0) ? pv[i].x : (t == 1) ? pv[i].y
                               : (t == 2) ? pv[i].z : pv[i].w;
                    if (!(fz & (1u << i))) {
                        unsigned long long kk = packkey(cand, lane + 32 * i);
                        if (kk > key) key = kk;
                    }
                }
                #pragma unroll
                for (int off = 16; off; off >>= 1) {
                    unsigned long long o = __shfl_xor_sync(0xffffffffu, key, off);
                    if (o > key) key = o;
                }
                const int prow  = (int)(key & 0xffffffffULL);
                const int plane = prow & 31;
                const int pi    = prow >> 5;
                prows[t] = prow;
                // broadcast pivot row vector
                tsel = (pi == 0) ? pv[0] : (pi == 1) ? pv[1]
                     : (pi == 2) ? pv[2] : pv[3];
                float4 pr4;
                pr4.x = __shfl_sync(0xffffffffu, tsel.x, plane);
                pr4.y = __shfl_sync(0xffffffffu, tsel.y, plane);
                pr4.z = __shfl_sync(0xffffffffu, tsel.z, plane);
                pr4.w = __shfl_sync(0xffffffffu, tsel.w, plane);
                if (lane == plane) fz |= (1u << pi);   // freeze pivot row
                float pd   = (t == 0) ? pr4.x : (t == 1) ? pr4.y
                           : (t == 2) ? pr4.z : pr4.w;
                float pinv = 1.f / pd;
                #pragma unroll
                for (int i = 0; i < 4; i++) {
                    if (!(fz & (1u << i))) {
                        if (t == 0) {
                            float m = pv[i].x * pinv; pv[i].x = m;
                            pv[i].y -= m * pr4.y;
                            pv[i].z -= m * pr4.z;
                            pv[i].w -= m * pr4.w;
                        } else if (t == 1) {
                            float m = pv[i].y * pinv; pv[i].y = m;
                            pv[i].z -= m * pr4.z;
                            pv[i].w -= m * pr4.w;
                        } else if (t == 2) {
                            float m = pv[i].z * pinv; pv[i].z = m;
                            pv[i].w -= m * pr4.w;
                        } else {
                            float m = pv[i].w * pinv; pv[i].w = m;
                        }
                    }
                }
            }

            // write panel back
            #pragma unroll
            for (int i = 0; i < 4; i++)
                *(float4*)(S + (lane + 32 * i) * STR + k0) = pv[i];

            // gather pivot-row multipliers, compose Phase-B coefficients
            {
                int p1 = prows[1], p2 = prows[2], p3 = prows[3];
                int i1 = p1 >> 5, i2 = p2 >> 5, i3 = p3 >> 5;
                float4 s1 = (i1 == 0) ? pv[0] : (i1 == 1) ? pv[1]
                          : (i1 == 2) ? pv[2] : pv[3];
                float4 s2 = (i2 == 0) ? pv[0] : (i2 == 1) ? pv[1]
                          : (i2 == 2) ? pv[2] : pv[3];
                float4 s3 = (i3 == 0) ? pv[0] : (i3 == 1) ? pv[1]
                          : (i3 == 2) ? pv[2] : pv[3];
                float m10 = __shfl_sync(0xffffffffu, s1.x, p1 & 31);
                float m20 = __shfl_sync(0xffffffffu, s2.x, p2 & 31);
                float m21 = __shfl_sync(0xffffffffu, s2.y, p2 & 31);
                float m30 = __shfl_sync(0xffffffffu, s3.x, p3 & 31);
                float m31 = __shfl_sync(0xffffffffu, s3.y, p3 & 31);
                float m32 = __shfl_sync(0xffffffffu, s3.z, p3 & 31);
                if (lane == 0) {
                    float c10 = -m10;
                    float c21 = -m21;
                    float c20 = -m20 + m21 * m10;
                    float c32 = -m32;
                    float c31 = -m31 + m32 * m21;
                    float c30 = -m30 + m31 * m10 - m32 * c20;
                    coef[0] = c10; coef[1] = c20; coef[2] = c21;
                    coef[3] = c30; coef[4] = c31; coef[5] = c32;
                    perm[k0 + 0] = prows[0];
                    perm[k0 + 1] = prows[1];
                    perm[k0 + 2] = prows[2];
                    perm[k0 + 3] = prows[3];
                }
            }
        }
        __syncthreads();       // (2) panel, perm, coef visible

        // ===== snapshot original pivot rows (trailing + rhs) ================
        const int cstart = (k0 >> 2) + 1;          // first trailing chunk
        const int nch    = 33 - cstart;            // trailing chunks incl rhs
        if (tid < 4 * nch) {
            int t  = tid / nch;
            int cc = cstart + tid % nch;
            *(float4*)(scratch + t * STR + 4 * cc) =
                *(const float4*)(S + perm[k0 + t] * STR + 4 * cc);
        }

        // ===== per-row composed coefficients ================================
        int ptype;             // -1 active, 0..3 pivot this panel, 4 done
        {
            ptype = rowactive ? -1 : 4;
            int pqx = perm[k0 + 0], pqy = perm[k0 + 1];
            int pqz = perm[k0 + 2], pqw = perm[k0 + 3];
            if (r == pqx) ptype = 0;
            else if (r == pqy) ptype = 1;
            else if (r == pqz) ptype = 2;
            else if (r == pqw) ptype = 3;
        }
        float e0 = 0.f, e1 = 0.f, e2 = 0.f, e3 = 0.f;
        if (ptype == -1) {
            float4 m = *(const float4*)(S + r * STR + k0);
            e0 = m.x + m.y * coef[0] + m.z * coef[1] + m.w * coef[3];
            e1 = m.y + m.z * coef[2] + m.w * coef[4];
            e2 = m.z + m.w * coef[5];
            e3 = m.w;
        } else if (ptype == 1) {
            e0 = -coef[0];
        } else if (ptype == 2) {
            e0 = -coef[1]; e1 = -coef[2];
        } else if (ptype == 3) {
            e0 = -coef[3]; e1 = -coef[4]; e2 = -coef[5];
        }
        __syncthreads();       // (3) scratch ready

        // ===== unified rank-4 trailing update ===============================
        if (ptype != 0 && ptype != 4) {
            float* Sr = S + r * STR;
            const float* P0 = scratch + 0 * STR;
            const float* P1 = scratch + 1 * STR;
            const float* P2 = scratch + 2 * STR;
            const float* P3 = scratch + 3 * STR;
            const bool firstowner = ((cstart & 1) == half);
            for (int c = cstart + (firstowner ? 0 : 1); c <= 32; c += 2) {
                float4 s  = *(const float4*)(Sr + 4 * c);
                float4 p0 = *(const float4*)(P0 + 4 * c);
                float4 p1 = *(const float4*)(P1 + 4 * c);
                float4 p2 = *(const float4*)(P2 + 4 * c);
                float4 p3 = *(const float4*)(P3 + 4 * c);
                s.x -= e0 * p0.x + e1 * p1.x + e2 * p2.x + e3 * p3.x;
                s.y -= e0 * p0.y + e1 * p1.y + e2 * p2.y + e3 * p3.y;
                s.z -= e0 * p0.z + e1 * p1.z + e2 * p2.z + e3 * p3.z;
                s.w -= e0 * p0.w + e1 * p1.w + e2 * p2.w + e3 * p3.w;
                *(float4*)(Sr + 4 * c) = s;
            }
        }
        if (ptype >= 0 && ptype <= 3) rowactive = false;
    }
    __syncthreads();

    // ---- back substitution (warp 0, no block barriers) ---------------------
    if (tid < 32) {
        int p0 = perm[tid],      p1 = perm[tid + 32];
        int p2 = perm[tid + 64], p3 = perm[tid + 96];
        for (int k = M4 - 1; k >= 0; k--) {
            int q = k >> 5, src = k & 31;
            int pk = (q == 0) ? p0 : (q == 1) ? p1 : (q == 2) ? p2 : p3;
            float cand = S[pk * STR + 128] / S[pk * STR + k];
            float lk = __shfl_sync(0xffffffffu, cand, src);
            if (tid == src) sol[k] = lk;
            if (tid      < k) S[p0 * STR + 128] -= S[p0 * STR + k] * lk;
            if (tid + 32 < k) S[p1 * STR + 128] -= S[p1 * STR + k] * lk;
            if (tid + 64 < k) S[p2 * STR + 128] -= S[p2 * STR + k] * lk;
            if (tid + 96 < k) S[p3 * STR + 128] -= S[p3 * STR + k] * lk;
            __syncwarp();
        }
    }
    __syncthreads();

    // ---- g = G^T l  (sparse scatter, smem atomics) -------------------------
    if (tid < 128) gacc[tid] = 0.f;
    __syncthreads();
    if (tid < NC) {
        int c = tid;
        float wn = sol[c];
        float wt = sol[NC + 2 * c] - sol[NC + 2 * c + 1];
        float wx = wn * en[c][0] + wt * et[c][0];
        float wy = wn * en[c][1] + wt * et[c][1];
        atomicAdd(&gacc[ii[c] * 2 + 0], -wx);
        atomicAdd(&gacc[ii[c] * 2 + 1], -wy);
        atomicAdd(&gacc[jj[c] * 2 + 0],  wx);
        atomicAdd(&gacc[jj[c] * 2 + 1],  wy);
    }
    __syncthreads();

    // ---- v_plus = v + W (g - reg*v) ----------------------------------------
    if (tid < 128) {
        int p = tid >> 1, s2 = tid & 1;
        float acc = 0.f;
        #pragma unroll 8
        for (int q = 0; q < 64; q++)
            acc += g_W[p * 64 + q] * (gacc[q * 2 + s2] - REG * vs[q][s2]);
        out[b * 256 + 128 + tid] = vs[p][s2] + acc;
    }
}

// ---------------------------------------------------------------------------
extern "C" void kernel_launch(void* const* d_in, const int* in_sizes, int n_in,
                              void* d_out, int out_size) {
    const float* x    = (const float*)d_in[0];
    const float* v    = (const float*)d_in[1];
    const int*   cld  = (const int*)  d_in[2];
    const float* dist = (const float*)d_in[3];
    const float* mu   = (const float*)d_in[4];
    const float* cor  = (const float*)d_in[5];
    const float* Minv = (const float*)d_in[6];
    float* out = (float*)d_out;

    int bs = out_size / 256;

    const size_t smem_bytes = M4 * STR * sizeof(float);  // 67584 B
    cudaFuncSetAttribute(solve_batch_kernel,
                         cudaFuncAttributeMaxDynamicSharedMemorySize,
                         (int)smem_bytes);

    // W = (I + reg*Minv)^{-1} Minv via Neumann series, column-parallel.
    // Device globals are accessed inside the kernels (mode param), never
    // passed as host-side symbol arguments.
    prep_T1_kernel<<<16, 256>>>(Minv);
    prep_mm_kernel<<<16, 256>>>(Minv, 0);   // T2 = I - rM*T1
    prep_mm_kernel<<<16, 256>>>(Minv, 1);   // T3 = I - rM*T2 (into g_T1)
    prep_mm_kernel<<<16, 256>>>(Minv, 2);   // W  = M*T3

    solve_batch_kernel<<<bs, 256, smem_bytes>>>(x, v, cld, dist, mu, cor, out);
}

// round 8
// speedup vs baseline: 5.6921x; 2.8989x over previous
#include <cuda_runtime.h>

// Problem constants (from reference): bs=1024, n=64, d=2, nc=32
#define NPART 64
#define ND    128          // n*d
#define NC    32
#define NR    64           // reduced system size: nc normal + nc tangent-diff
#define REG   1e-3f
#define STR   68           // padded row stride (floats): 64 cols + rhs + 3 pad

// Precomputed W = (Minv^{-1} + reg I)^{-1} = (I + reg*Minv)^{-1} Minv  (64x64)
__device__ float g_W[NPART * NPART];
__device__ float g_T1[NPART * NPART];
__device__ float g_T2[NPART * NPART];

static __device__ __forceinline__ unsigned long long packkey(float v, int r) {
    return (((unsigned long long)__float_as_uint(fabsf(v))) << 32) | (unsigned)r;
}

// ---------------------------------------------------------------------------
// Prep: W via 4-term Neumann/Horner series (reg*||Minv|| ~ 5e-3 ->
// truncation ~7e-10). Column-parallel across 16 CTAs per step. Device
// globals referenced in DEVICE code only (host-side symbol args bind the
// host shadow variable -> ATS-silent corruption; see R5/R6).
// ---------------------------------------------------------------------------
__global__ void prep_T1_kernel(const float* __restrict__ Minv) {
    int idx = blockIdx.x * 256 + threadIdx.x;
    int r = idx >> 6, c = idx & 63;
    g_T1[idx] = ((r == c) ? 1.f : 0.f) - REG * Minv[idx];
}

// mode 0: g_T2 = I - reg*M@g_T1 ; mode 1: g_T1 = I - reg*M@g_T2 ; mode 2: g_W = M@g_T1
__global__ void prep_mm_kernel(const float* __restrict__ Minv, int mode) {
    int idx = blockIdx.x * 256 + threadIdx.x;
    int r = idx >> 6, c = idx & 63;
    const float* src = (mode == 1) ? g_T2 : g_T1;
    float acc = 0.f;
    #pragma unroll 8
    for (int b = 0; b < 64; b++) acc += Minv[r * 64 + b] * src[b * 64 + c];
    if (mode == 0)      g_T2[idx] = ((r == c) ? 1.f : 0.f) - REG * acc;
    else if (mode == 1) g_T1[idx] = ((r == c) ? 1.f : 0.f) - REG * acc;
    else                g_W[idx]  = acc;
}

// ---------------------------------------------------------------------------
// Kernel B: one CTA (256 threads) per batch element.
// EXACT reduction of the 256x256 KKT to a 64x64 system in (lambda_n, u):
//   A[r][s] = -(d_r . d_s) kappa[cr][cs] + diag(REG for normal, REG/2 tangent)
// (tangent +/- pair rows summed -> lambda+ + lambda- = 2*gamma/REG; gamma row
//  eliminates gamma; mu cancels exactly from the (lambda_n,u) system, and
//  v_plus depends only on lambda_n and u = lambda+ - lambda-.)
// Blocked LU (panel 4, in-register warp-0 factorization) with permutation
// pivoting, rank-4 float4 trailing updates, 3 barriers/panel, 16 panels.
// ---------------------------------------------------------------------------
__global__ void __launch_bounds__(256)
solve_batch_kernel(const float* __restrict__ x, const float* __restrict__ v,
                   const int* __restrict__ cld, const float* __restrict__ dist,
                   const float* __restrict__ mu, const float* __restrict__ cor,
                   float* __restrict__ out) {
    __shared__ float S[NR * STR];         // 64*68*4 = 17408 B
    __shared__ float kappa[NC][NC];       // reused: pivot-row scratch, then gacc
    __shared__ float en[NC][2], et[NC][2];
    __shared__ int   ii[NC], jj[NC];
    __shared__ float hs[NC];
    __shared__ float vs[NPART][2];
    __shared__ float ys[NPART][2];        // reused as sol
    __shared__ int   perm[NR];
    __shared__ float coef[6];             // c10,c20,c21,c30,c31,c32

    float* sol     = &ys[0][0];
    float* gacc    = &kappa[0][0];
    float* scratch = &kappa[0][0];        // 4 x 68 floats = 1088 B (< 4 KB)

    const int b    = blockIdx.x;
    const int tid  = threadIdx.x;
    const int r    = tid & 63;            // row 0..63
    const int qt   = tid >> 6;            // column quarter 0..3
    const float* xb = x + b * ND;
    const float* vb = v + b * ND;

    // ---- load + per-contact geometry -------------------------------------
    if (tid < 128) {
        out[b * 256 + tid] = xb[tid];            // x passes through unchanged
        vs[tid >> 1][tid & 1] = vb[tid];
    }
    if (tid < NC) {
        int c = tid;
        int i = cld[b * (NC * 2) + c * 2 + 0];
        int j = cld[b * (NC * 2) + c * 2 + 1];
        ii[c] = i; jj[c] = j;
        float dx = xb[j * 2 + 0] - xb[i * 2 + 0];
        float dy = xb[j * 2 + 1] - xb[i * 2 + 1];
        float inv = rsqrtf(dx * dx + dy * dy);
        float ex = dx * inv, ey = dy * inv;
        en[c][0] = ex;  en[c][1] = ey;
        et[c][0] = -ey; et[c][1] = ex;
        float jv = ex * (vb[j * 2] - vb[i * 2]) + ey * (vb[j * 2 + 1] - vb[i * 2 + 1]);
        hs[c] = fminf(dist[b * NC + c] * 12.5f, cor[b * NC + c] * jv);  // dist/(DT*8)
    }
    __syncthreads();

    // ---- kappa[cr][cs] = W[ii,is] - W[ii,js] - W[ji,is] + W[ji,js] --------
    for (int idx = tid; idx < NC * NC; idx += 256) {
        int cr = idx >> 5, cs = idx & 31;
        int ir = ii[cr], jr = jj[cr], is = ii[cs], js = jj[cs];
        kappa[cr][cs] = g_W[ir * 64 + is] - g_W[ir * 64 + js]
                      - g_W[jr * 64 + is] + g_W[jr * 64 + js];
    }

    // ---- y = A^{-1} r1 = -v + reg * (W v) ---------------------------------
    if (tid < 128) {
        int p = tid >> 1, s2 = tid & 1;
        float acc = 0.f;
        #pragma unroll 8
        for (int q = 0; q < 64; q++) acc += g_W[p * 64 + q] * vs[q][s2];
        ys[p][s2] = -vs[p][s2] + REG * acc;
    }
    __syncthreads();

    // ---- build reduced 64x64 system, rhs at col 64 ------------------------
    {
        const int cr = r & 31;
        const float drx = (r < 32) ? en[cr][0] : et[cr][0];
        const float dry = (r < 32) ? en[cr][1] : et[cr][1];
        for (int c = qt; c < STR; c += 4) {
            float val;
            if (c < 64) {
                int cs = c & 31;
                float dsx = (c < 32) ? en[cs][0] : et[cs][0];
                float dsy = (c < 32) ? en[cs][1] : et[cs][1];
                val = -(drx * dsx + dry * dsy) * kappa[cr][cs];
                if (c == r) val += (r < 32) ? REG : (0.5f * REG);
            } else if (c == 64) {
                float dx = ys[jj[cr]][0] - ys[ii[cr]][0];
                float dy = ys[jj[cr]][1] - ys[ii[cr]][1];
                val = -(drx * dx + dry * dy);
                if (r < 32) val -= hs[r];
            } else {
                val = 0.f;                                        // pad cols
            }
            S[r * STR + c] = val;
        }
    }

    // ---- blocked LU: in-register panel + unified rank-4 update -------------
    bool rowactive = true;     // per thread; row not yet pivoted
    unsigned fz = 0;           // warp 0 only: frozen mask for its 2 rows

    for (int k0 = 0; k0 < NR; k0 += 4) {
        __syncthreads();       // (1) previous trailing update / build complete

        // ===== panel factorization, warp 0, registers only =================
        if (tid < 32) {
            const int lane = tid;
            float4 pv[2];
            pv[0] = *(const float4*)(S + lane * STR + k0);
            pv[1] = *(const float4*)(S + (lane + 32) * STR + k0);

            int prows[4];

            #pragma unroll
            for (int t = 0; t < 4; t++) {
                unsigned long long key = 0;
                #pragma unroll
                for (int i = 0; i < 2; i++) {
                    float cand = (t == 0) ? pv[i].x : (t == 1) ? pv[i].y
                               : (t == 2) ? pv[i].z : pv[i].w;
                    if (!(fz & (1u << i))) {
                        unsigned long long kk = packkey(cand, lane + 32 * i);
                        if (kk > key) key = kk;
                    }
                }
                #pragma unroll
                for (int off = 16; off; off >>= 1) {
                    unsigned long long o = __shfl_xor_sync(0xffffffffu, key, off);
                    if (o > key) key = o;
                }
                const int prow  = (int)(key & 0xffffffffULL);
                const int plane = prow & 31;
                const int pi    = prow >> 5;
                prows[t] = prow;
                float4 tsel = pi ? pv[1] : pv[0];
                float4 pr4;
                pr4.x = __shfl_sync(0xffffffffu, tsel.x, plane);
                pr4.y = __shfl_sync(0xffffffffu, tsel.y, plane);
                pr4.z = __shfl_sync(0xffffffffu, tsel.z, plane);
                pr4.w = __shfl_sync(0xffffffffu, tsel.w, plane);
                if (lane == plane) fz |= (1u << pi);   // freeze pivot row
                float pd   = (t == 0) ? pr4.x : (t == 1) ? pr4.y
                           : (t == 2) ? pr4.z : pr4.w;
                float pinv = 1.f / pd;
                #pragma unroll
                for (int i = 0; i < 2; i++) {
                    if (!(fz & (1u << i))) {
                        if (t == 0) {
                            float m = pv[i].x * pinv; pv[i].x = m;
                            pv[i].y -= m * pr4.y;
                            pv[i].z -= m * pr4.z;
                            pv[i].w -= m * pr4.w;
                        } else if (t == 1) {
                            float m = pv[i].y * pinv; pv[i].y = m;
                            pv[i].z -= m * pr4.z;
                            pv[i].w -= m * pr4.w;
                        } else if (t == 2) {
                            float m = pv[i].z * pinv; pv[i].z = m;
                            pv[i].w -= m * pr4.w;
                        } else {
                            float m = pv[i].w * pinv; pv[i].w = m;
                        }
                    }
                }
            }

            *(float4*)(S + lane * STR + k0)        = pv[0];
            *(float4*)(S + (lane + 32) * STR + k0) = pv[1];

            // gather pivot-row multipliers, compose correction coefficients
            {
                int p1 = prows[1], p2 = prows[2], p3 = prows[3];
                float4 s1 = (p1 >> 5) ? pv[1] : pv[0];
                float4 s2 = (p2 >> 5) ? pv[1] : pv[0];
                float4 s3 = (p3 >> 5) ? pv[1] : pv[0];
                float m10 = __shfl_sync(0xffffffffu, s1.x, p1 & 31);
                float m20 = __shfl_sync(0xffffffffu, s2.x, p2 & 31);
                float m21 = __shfl_sync(0xffffffffu, s2.y, p2 & 31);
                float m30 = __shfl_sync(0xffffffffu, s3.x, p3 & 31);
                float m31 = __shfl_sync(0xffffffffu, s3.y, p3 & 31);
                float m32 = __shfl_sync(0xffffffffu, s3.z, p3 & 31);
                if (lane == 0) {
                    float c10 = -m10;
                    float c21 = -m21;
                    float c20 = -m20 + m21 * m10;
                    float c32 = -m32;
                    float c31 = -m31 + m32 * m21;
                    float c30 = -m30 + m31 * m10 - m32 * c20;
                    coef[0] = c10; coef[1] = c20; coef[2] = c21;
                    coef[3] = c30; coef[4] = c31; coef[5] = c32;
                    perm[k0 + 0] = prows[0];
                    perm[k0 + 1] = prows[1];
                    perm[k0 + 2] = prows[2];
                    perm[k0 + 3] = prows[3];
                }
            }
        }
        __syncthreads();       // (2) panel, perm, coef visible

        // ===== snapshot original pivot rows (trailing + rhs) ================
        const int cstart = (k0 >> 2) + 1;          // first trailing chunk
        const int nch    = 17 - cstart;            // trailing chunks incl rhs
        if (tid < 4 * nch) {
            int t  = tid / nch;
            int cc = cstart + tid % nch;
            *(float4*)(scratch + t * STR + 4 * cc) =
                *(const float4*)(S + perm[k0 + t] * STR + 4 * cc);
        }

        // ===== per-row composed coefficients ================================
        int ptype;             // -1 active, 0..3 pivot this panel, 4 done
        {
            ptype = rowactive ? -1 : 4;
            if      (r == perm[k0 + 0]) ptype = 0;
            else if (r == perm[k0 + 1]) ptype = 1;
            else if (r == perm[k0 + 2]) ptype = 2;
            else if (r == perm[k0 + 3]) ptype = 3;
        }
        float e0 = 0.f, e1 = 0.f, e2 = 0.f, e3 = 0.f;
        if (ptype == -1) {
            float4 m = *(const float4*)(S + r * STR + k0);
            e0 = m.x + m.y * coef[0] + m.z * coef[1] + m.w * coef[3];
            e1 = m.y + m.z * coef[2] + m.w * coef[4];
            e2 = m.z + m.w * coef[5];
            e3 = m.w;
        } else if (ptype == 1) {
            e0 = -coef[0];
        } else if (ptype == 2) {
            e0 = -coef[1]; e1 = -coef[2];
        } else if (ptype == 3) {
            e0 = -coef[3]; e1 = -coef[4]; e2 = -coef[5];
        }
        __syncthreads();       // (3) scratch ready

        // ===== unified rank-4 trailing update (4 threads per row) ==========
        if (ptype != 0 && ptype != 4) {
            float* Sr = S + r * STR;
            const float* P0 = scratch + 0 * STR;
            const float* P1 = scratch + 1 * STR;
            const float* P2 = scratch + 2 * STR;
            const float* P3 = scratch + 3 * STR;
            for (int c = cstart + qt; c <= 16; c += 4) {
                float4 s  = *(const float4*)(Sr + 4 * c);
                float4 p0 = *(const float4*)(P0 + 4 * c);
                float4 p1 = *(const float4*)(P1 + 4 * c);
                float4 p2 = *(const float4*)(P2 + 4 * c);
                float4 p3 = *(const float4*)(P3 + 4 * c);
                s.x -= e0 * p0.x + e1 * p1.x + e2 * p2.x + e3 * p3.x;
                s.y -= e0 * p0.y + e1 * p1.y + e2 * p2.y + e3 * p3.y;
                s.z -= e0 * p0.z + e1 * p1.z + e2 * p2.z + e3 * p3.z;
                s.w -= e0 * p0.w + e1 * p1.w + e2 * p2.w + e3 * p3.w;
                *(float4*)(Sr + 4 * c) = s;
            }
        }
        if (ptype >= 0 && ptype <= 3) rowactive = false;
    }
    __syncthreads();

    // ---- back substitution (warp 0, no block barriers) ---------------------
    if (tid < 32) {
        int p0 = perm[tid], p1 = perm[tid + 32];
        for (int k = NR - 1; k >= 0; k--) {
            int src = k & 31;
            int pk  = (k >= 32) ? p1 : p0;
            float cand = S[pk * STR + 64] / S[pk * STR + k];
            float lk = __shfl_sync(0xffffffffu, cand, src);
            if (tid == src) sol[k] = lk;
            if (tid      < k) S[p0 * STR + 64] -= S[p0 * STR + k] * lk;
            if (tid + 32 < k) S[p1 * STR + 64] -= S[p1 * STR + k] * lk;
            __syncwarp();
        }
    }
    __syncthreads();

    // ---- g = G^T l  (wn = lambda_n, wt = u = lambda+ - lambda-) -------------
    if (tid < 128) gacc[tid] = 0.f;
    __syncthreads();
    if (tid < NC) {
        int c = tid;
        float wn = sol[c];
        float wt = sol[NC + c];
        float wx = wn * en[c][0] + wt * et[c][0];
        float wy = wn * en[c][1] + wt * et[c][1];
        atomicAdd(&gacc[ii[c] * 2 + 0], -wx);
        atomicAdd(&gacc[ii[c] * 2 + 1], -wy);
        atomicAdd(&gacc[jj[c] * 2 + 0],  wx);
        atomicAdd(&gacc[jj[c] * 2 + 1],  wy);
    }
    __syncthreads();

    // ---- v_plus = v + W (g - reg*v) ----------------------------------------
    if (tid < 128) {
        int p = tid >> 1, s2 = tid & 1;
        float acc = 0.f;
        #pragma unroll 8
        for (int q = 0; q < 64; q++)
            acc += g_W[p * 64 + q] * (gacc[q * 2 + s2] - REG * vs[q][s2]);
        out[b * 256 + 128 + tid] = vs[p][s2] + acc;
    }
}

// ---------------------------------------------------------------------------
extern "C" void kernel_launch(void* const* d_in, const int* in_sizes, int n_in,
                              void* d_out, int out_size) {
    const float* x    = (const float*)d_in[0];
    const float* v    = (const float*)d_in[1];
    const int*   cld  = (const int*)  d_in[2];
    const float* dist = (const float*)d_in[3];
    const float* mu   = (const float*)d_in[4];
    const float* cor  = (const float*)d_in[5];
    const float* Minv = (const float*)d_in[6];
    float* out = (float*)d_out;

    int bs = out_size / 256;

    // W = (I + reg*Minv)^{-1} Minv via Neumann series, column-parallel.
    prep_T1_kernel<<<16, 256>>>(Minv);
    prep_mm_kernel<<<16, 256>>>(Minv, 0);   // T2 = I - rM*T1
    prep_mm_kernel<<<16, 256>>>(Minv, 1);   // T3 = I - rM*T2 (into g_T1)
    prep_mm_kernel<<<16, 256>>>(Minv, 2);   // W  = M*T3

    solve_batch_kernel<<<bs, 256>>>(x, v, cld, dist, mu, cor, out);
}

// round 10
// speedup vs baseline: 5.9194x; 1.0399x over previous
#include <cuda_runtime.h>

// Problem constants (from reference): bs=1024, n=64, d=2, nc=32
#define NPART 64
#define ND    128          // n*d
#define NC    32
#define NR    64           // reduced system size: nc normal + nc tangent-diff
#define REG   1e-3f
#define STR   68           // padded row stride (floats): 64 cols + rhs + 3 pad
#define WSTR  65           // smem W stride (conflict-free padding)

// Precomputed W = (Minv^{-1} + reg I)^{-1} = (I + reg*Minv)^{-1} Minv  (64x64)
__device__ float g_W[NPART * NPART];

static __device__ __forceinline__ unsigned long long packkey(float v, int r) {
    return (((unsigned long long)__float_as_uint(fabsf(v))) << 32) | (unsigned)r;
}

// ---------------------------------------------------------------------------
// Prep (single launch): W via 4-term Neumann/Horner series
// (reg*||Minv|| ~ 5e-3 -> truncation ~7e-10). One CTA, 1024 threads,
// intermediates staged in padded smem (LDS conflict-free; Minv row reads are
// warp-broadcast L1 hits). Device global g_W referenced in device code only.
// ---------------------------------------------------------------------------
__global__ void __launch_bounds__(1024)
prep_W_fused(const float* __restrict__ Minv) {
    __shared__ float A[64 * WSTR];
    __shared__ float B[64 * WSTR];
    const int tid = threadIdx.x;

    // A = I - reg*M
    for (int idx = tid; idx < 4096; idx += 1024) {
        int r = idx >> 6, c = idx & 63;
        A[r * WSTR + c] = ((r == c) ? 1.f : 0.f) - REG * Minv[idx];
    }
    __syncthreads();
    // B = I - reg*M@A
    for (int idx = tid; idx < 4096; idx += 1024) {
        int r = idx >> 6, c = idx & 63;
        float acc = 0.f;
        #pragma unroll 8
        for (int b2 = 0; b2 < 64; b2++) acc += Minv[r * 64 + b2] * A[b2 * WSTR + c];
        B[r * WSTR + c] = ((r == c) ? 1.f : 0.f) - REG * acc;
    }
    __syncthreads();
    // A = I - reg*M@B
    for (int idx = tid; idx < 4096; idx += 1024) {
        int r = idx >> 6, c = idx & 63;
        float acc = 0.f;
        #pragma unroll 8
        for (int b2 = 0; b2 < 64; b2++) acc += Minv[r * 64 + b2] * B[b2 * WSTR + c];
        A[r * WSTR + c] = ((r == c) ? 1.f : 0.f) - REG * acc;
    }
    __syncthreads();
    // g_W = M@A
    for (int idx = tid; idx < 4096; idx += 1024) {
        int r = idx >> 6, c = idx & 63;
        float acc = 0.f;
        #pragma unroll 8
        for (int b2 = 0; b2 < 64; b2++) acc += Minv[r * 64 + b2] * A[b2 * WSTR + c];
        g_W[idx] = acc;
    }
}

// ---------------------------------------------------------------------------
// Kernel B: one CTA (256 threads) per batch element.
// Exact reduction of the 256x256 KKT to a 64x64 system in (lambda_n, u);
// W is staged in smem (padded, conflict-free), ALIASED into the S buffer:
//   load W -> kappa + y matvec (LDS) -> S build overwrites -> LU ->
//   back-sub -> reload W -> final matvec (LDS).
// Blocked LU (panel 4, in-register warp-0 factorization) with permutation
// pivoting, rank-4 float4 trailing updates, 3 barriers/panel, 16 panels.
// ---------------------------------------------------------------------------
__global__ void __launch_bounds__(256)
solve_batch_kernel(const float* __restrict__ x, const float* __restrict__ v,
                   const int* __restrict__ cld, const float* __restrict__ dist,
                   const float* __restrict__ mu, const float* __restrict__ cor,
                   float* __restrict__ out) {
    __shared__ float S[NR * STR];         // 64*68*4 = 17408 B; W overlay 64*65
    __shared__ float kappa[NC][NC];       // reused: pivot-row scratch, then gacc
    __shared__ float en[NC][2], et[NC][2];
    __shared__ int   ii[NC], jj[NC];
    __shared__ float hs[NC];
    __shared__ float vs[NPART][2];
    __shared__ float ys[NPART][2];        // reused as sol
    __shared__ int   perm[NR];
    __shared__ float coef[6];             // c10,c20,c21,c30,c31,c32

    float* Wsm     = S;                   // 64*65 = 4160 floats <= 4352
    float* sol     = &ys[0][0];
    float* gacc    = &kappa[0][0];
    float* scratch = &kappa[0][0];        // 4 x 68 floats = 1088 B (< 4 KB)

    const int b    = blockIdx.x;
    const int tid  = threadIdx.x;
    const int r    = tid & 63;            // row 0..63
    const int qt   = tid >> 6;            // column quarter 0..3
    const float* xb = x + b * ND;
    const float* vb = v + b * ND;

    // ---- stage W into smem (coalesced) + load + per-contact geometry ------
    for (int idx = tid; idx < 4096; idx += 256)
        Wsm[(idx >> 6) * WSTR + (idx & 63)] = g_W[idx];
    if (tid < 128) {
        out[b * 256 + tid] = xb[tid];            // x passes through unchanged
        vs[tid >> 1][tid & 1] = vb[tid];
    }
    if (tid < NC) {
        int c = tid;
        int i = cld[b * (NC * 2) + c * 2 + 0];
        int j = cld[b * (NC * 2) + c * 2 + 1];
        ii[c] = i; jj[c] = j;
        float dx = xb[j * 2 + 0] - xb[i * 2 + 0];
        float dy = xb[j * 2 + 1] - xb[i * 2 + 1];
        float inv = rsqrtf(dx * dx + dy * dy);
        float ex = dx * inv, ey = dy * inv;
        en[c][0] = ex;  en[c][1] = ey;
        et[c][0] = -ey; et[c][1] = ex;
        float jv = ex * (vb[j * 2] - vb[i * 2]) + ey * (vb[j * 2 + 1] - vb[i * 2 + 1]);
        hs[c] = fminf(dist[b * NC + c] * 12.5f, cor[b * NC + c] * jv);  // dist/(DT*8)
    }
    __syncthreads();

    // ---- kappa[cr][cs] from smem W ----------------------------------------
    for (int idx = tid; idx < NC * NC; idx += 256) {
        int cr = idx >> 5, cs = idx & 31;
        int ir = ii[cr], jr = jj[cr], is = ii[cs], js = jj[cs];
        kappa[cr][cs] = Wsm[ir * WSTR + is] - Wsm[ir * WSTR + js]
                      - Wsm[jr * WSTR + is] + Wsm[jr * WSTR + js];
    }

    // ---- y = -v + reg * (W v)  (smem W, conflict-free) ---------------------
    if (tid < 128) {
        int p = tid >> 1, s2 = tid & 1;
        float acc = 0.f;
        #pragma unroll 8
        for (int q = 0; q < 64; q++) acc += Wsm[p * WSTR + q] * vs[q][s2];
        ys[p][s2] = -vs[p][s2] + REG * acc;
    }
    __syncthreads();       // all Wsm reads done before S build overwrites

    // ---- build reduced 64x64 system, rhs at col 64 (overwrites Wsm) --------
    {
        const int cr = r & 31;
        const float drx = (r < 32) ? en[cr][0] : et[cr][0];
        const float dry = (r < 32) ? en[cr][1] : et[cr][1];
        for (int c = qt; c < STR; c += 4) {
            float val;
            if (c < 64) {
                int cs = c & 31;
                float dsx = (c < 32) ? en[cs][0] : et[cs][0];
                float dsy = (c < 32) ? en[cs][1] : et[cs][1];
                val = -(drx * dsx + dry * dsy) * kappa[cr][cs];
                if (c == r) val += (r < 32) ? REG : (0.5f * REG);
            } else if (c == 64) {
                float dx = ys[jj[cr]][0] - ys[ii[cr]][0];
                float dy = ys[jj[cr]][1] - ys[ii[cr]][1];
                val = -(drx * dx + dry * dy);
                if (r < 32) val -= hs[r];
            } else {
                val = 0.f;                                        // pad cols
            }
            S[r * STR + c] = val;
        }
    }

    // ---- blocked LU: in-register panel + unified rank-4 update -------------
    bool rowactive = true;     // per thread; row not yet pivoted
    unsigned fz = 0;           // warp 0 only: frozen mask for its 2 rows

    for (int k0 = 0; k0 < NR; k0 += 4) {
        __syncthreads();       // (1) previous trailing update / build complete

        // ===== panel factorization, warp 0, registers only =================
        if (tid < 32) {
            const int lane = tid;
            float4 pv[2];
            pv[0] = *(const float4*)(S + lane * STR + k0);
            pv[1] = *(const float4*)(S + (lane + 32) * STR + k0);

            int prows[4];

            #pragma unroll
            for (int t = 0; t < 4; t++) {
                unsigned long long key = 0;
                #pragma unroll
                for (int i = 0; i < 2; i++) {
                    float cand = (t == 0) ? pv[i].x : (t == 1) ? pv[i].y
                               : (t == 2) ? pv[i].z : pv[i].w;
                    if (!(fz & (1u << i))) {
                        unsigned long long kk = packkey(cand, lane + 32 * i);
                        if (kk > key) key = kk;
                    }
                }
                #pragma unroll
                for (int off = 16; off; off >>= 1) {
                    unsigned long long o = __shfl_xor_sync(0xffffffffu, key, off);
                    if (o > key) key = o;
                }
                const int prow  = (int)(key & 0xffffffffULL);
                const int plane = prow & 31;
                const int pi    = prow >> 5;
                prows[t] = prow;
                float4 tsel = pi ? pv[1] : pv[0];
                float4 pr4;
                pr4.x = __shfl_sync(0xffffffffu, tsel.x, plane);
                pr4.y = __shfl_sync(0xffffffffu, tsel.y, plane);
                pr4.z = __shfl_sync(0xffffffffu, tsel.z, plane);
                pr4.w = __shfl_sync(0xffffffffu, tsel.w, plane);
                if (lane == plane) fz |= (1u << pi);   // freeze pivot row
                float pd   = (t == 0) ? pr4.x : (t == 1) ? pr4.y
                           : (t == 2) ? pr4.z : pr4.w;
                float pinv = 1.f / pd;
                #pragma unroll
                for (int i = 0; i < 2; i++) {
                    if (!(fz & (1u << i))) {
                        if (t == 0) {
                            float m = pv[i].x * pinv; pv[i].x = m;
                            pv[i].y -= m * pr4.y;
                            pv[i].z -= m * pr4.z;
                            pv[i].w -= m * pr4.w;
                        } else if (t == 1) {
                            float m = pv[i].y * pinv; pv[i].y = m;
                            pv[i].z -= m * pr4.z;
                            pv[i].w -= m * pr4.w;
                        } else if (t == 2) {
                            float m = pv[i].z * pinv; pv[i].z = m;
                            pv[i].w -= m * pr4.w;
                        } else {
                            float m = pv[i].w * pinv; pv[i].w = m;
                        }
                    }
                }
            }

            *(float4*)(S + lane * STR + k0)        = pv[0];
            *(float4*)(S + (lane + 32) * STR + k0) = pv[1];

            // gather pivot-row multipliers, compose correction coefficients
            {
                int p1 = prows[1], p2 = prows[2], p3 = prows[3];
                float4 s1 = (p1 >> 5) ? pv[1] : pv[0];
                float4 s2 = (p2 >> 5) ? pv[1] : pv[0];
                float4 s3 = (p3 >> 5) ? pv[1] : pv[0];
                float m10 = __shfl_sync(0xffffffffu, s1.x, p1 & 31);
                float m20 = __shfl_sync(0xffffffffu, s2.x, p2 & 31);
                float m21 = __shfl_sync(0xffffffffu, s2.y, p2 & 31);
                float m30 = __shfl_sync(0xffffffffu, s3.x, p3 & 31);
                float m31 = __shfl_sync(0xffffffffu, s3.y, p3 & 31);
                float m32 = __shfl_sync(0xffffffffu, s3.z, p3 & 31);
                if (lane == 0) {
                    float c10 = -m10;
                    float c21 = -m21;
                    float c20 = -m20 + m21 * m10;
                    float c32 = -m32;
                    float c31 = -m31 + m32 * m21;
                    float c30 = -m30 + m31 * m10 - m32 * c20;
                    coef[0] = c10; coef[1] = c20; coef[2] = c21;
                    coef[3] = c30; coef[4] = c31; coef[5] = c32;
                    perm[k0 + 0] = prows[0];
                    perm[k0 + 1] = prows[1];
                    perm[k0 + 2] = prows[2];
                    perm[k0 + 3] = prows[3];
                }
            }
        }
        __syncthreads();       // (2) panel, perm, coef visible

        // ===== snapshot original pivot rows (trailing + rhs) ================
        const int cstart = (k0 >> 2) + 1;          // first trailing chunk
        const int nch    = 17 - cstart;            // trailing chunks incl rhs
        if (tid < 4 * nch) {
            int t  = tid / nch;
            int cc = cstart + tid % nch;
            *(float4*)(scratch + t * STR + 4 * cc) =
                *(const float4*)(S + perm[k0 + t] * STR + 4 * cc);
        }

        // ===== per-row composed coefficients ================================
        int ptype;             // -1 active, 0..3 pivot this panel, 4 done
        {
            ptype = rowactive ? -1 : 4;
            if      (r == perm[k0 + 0]) ptype = 0;
            else if (r == perm[k0 + 1]) ptype = 1;
            else if (r == perm[k0 + 2]) ptype = 2;
            else if (r == perm[k0 + 3]) ptype = 3;
        }
        float e0 = 0.f, e1 = 0.f, e2 = 0.f, e3 = 0.f;
        if (ptype == -1) {
            float4 m = *(const float4*)(S + r * STR + k0);
            e0 = m.x + m.y * coef[0] + m.z * coef[1] + m.w * coef[3];
            e1 = m.y + m.z * coef[2] + m.w * coef[4];
            e2 = m.z + m.w * coef[5];
            e3 = m.w;
        } else if (ptype == 1) {
            e0 = -coef[0];
        } else if (ptype == 2) {
            e0 = -coef[1]; e1 = -coef[2];
        } else if (ptype == 3) {
            e0 = -coef[3]; e1 = -coef[4]; e2 = -coef[5];
        }
        __syncthreads();       // (3) scratch ready

        // ===== unified rank-4 trailing update (4 threads per row) ==========
        if (ptype != 0 && ptype != 4) {
            float* Sr = S + r * STR;
            const float* P0 = scratch + 0 * STR;
            const float* P1 = scratch + 1 * STR;
            const float* P2 = scratch + 2 * STR;
            const float* P3 = scratch + 3 * STR;
            for (int c = cstart + qt; c <= 16; c += 4) {
                float4 s  = *(const float4*)(Sr + 4 * c);
                float4 p0 = *(const float4*)(P0 + 4 * c);
                float4 p1 = *(const float4*)(P1 + 4 * c);
                float4 p2 = *(const float4*)(P2 + 4 * c);
                float4 p3 = *(const float4*)(P3 + 4 * c);
                s.x -= e0 * p0.x + e1 * p1.x + e2 * p2.x + e3 * p3.x;
                s.y -= e0 * p0.y + e1 * p1.y + e2 * p2.y + e3 * p3.y;
                s.z -= e0 * p0.z + e1 * p1.z + e2 * p2.z + e3 * p3.z;
                s.w -= e0 * p0.w + e1 * p1.w + e2 * p2.w + e3 * p3.w;
                *(float4*)(Sr + 4 * c) = s;
            }
        }
        if (ptype >= 0 && ptype <= 3) rowactive = false;
    }
    __syncthreads();

    // ---- back substitution (warp 0, no block barriers) ---------------------
    if (tid < 32) {
        int p0 = perm[tid], p1 = perm[tid + 32];
        for (int k = NR - 1; k >= 0; k--) {
            int src = k & 31;
            int pk  = (k >= 32) ? p1 : p0;
            float cand = S[pk * STR + 64] / S[pk * STR + k];
            float lk = __shfl_sync(0xffffffffu, cand, src);
            if (tid == src) sol[k] = lk;
            if (tid      < k) S[p0 * STR + 64] -= S[p0 * STR + k] * lk;
            if (tid + 32 < k) S[p1 * STR + 64] -= S[p1 * STR + k] * lk;
            __syncwarp();
        }
    }
    __syncthreads();

    // ---- reload W (S region dead) + g = G^T l scatter -----------------------
    for (int idx = tid; idx < 4096; idx += 256)
        Wsm[(idx >> 6) * WSTR + (idx & 63)] = g_W[idx];
    if (tid < 128) gacc[tid] = 0.f;
    __syncthreads();
    if (tid < NC) {
        int c = tid;
        float wn = sol[c];                 // lambda_n
        float wt = sol[NC + c];            // u = lambda+ - lambda-
        float wx = wn * en[c][0] + wt * et[c][0];
        float wy = wn * en[c][1] + wt * et[c][1];
        atomicAdd(&gacc[ii[c] * 2 + 0], -wx);
        atomicAdd(&gacc[ii[c] * 2 + 1], -wy);
        atomicAdd(&gacc[jj[c] * 2 + 0],  wx);
        atomicAdd(&gacc[jj[c] * 2 + 1],  wy);
    }
    __syncthreads();

    // ---- v_plus = v + W (g - reg*v)  (smem W) -------------------------------
    if (tid < 128) {
        int p = tid >> 1, s2 = tid & 1;
        float acc = 0.f;
        #pragma unroll 8
        for (int q = 0; q < 64; q++)
            acc += Wsm[p * WSTR + q] * (gacc[q * 2 + s2] - REG * vs[q][s2]);
        out[b * 256 + 128 + tid] = vs[p][s2] + acc;
    }
}

// ---------------------------------------------------------------------------
extern "C" void kernel_launch(void* const* d_in, const int* in_sizes, int n_in,
                              void* d_out, int out_size) {
    const float* x    = (const float*)d_in[0];
    const float* v    = (const float*)d_in[1];
    const int*   cld  = (const int*)  d_in[2];
    const float* dist = (const float*)d_in[3];
    const float* mu   = (const float*)d_in[4];
    const float* cor  = (const float*)d_in[5];
    const float* Minv = (const float*)d_in[6];
    float* out = (float*)d_out;

    int bs = out_size / 256;

    prep_W_fused<<<1, 1024>>>(Minv);
    solve_batch_kernel<<<bs, 256>>>(x, v, cld, dist, mu, cor, out);
}

// round 12
// speedup vs baseline: 8.1374x; 1.3747x over previous
#include <cuda_runtime.h>

// Problem constants (from reference): bs=1024, n=64, d=2, nc=32
#define NPART 64
#define ND    128          // n*d
#define NC    32
#define NR    64           // reduced system size: nc normal + nc tangent-diff
#define REG   1e-3f
#define STR   68           // padded row stride (floats): 64 cols + rhs + 3 pad
#define WSTR  65           // smem W stride (conflict-free padding)

// Precomputed W = (Minv^{-1} + reg I)^{-1} = (I + reg*Minv)^{-1} Minv  (64x64)
__device__ float g_W[NPART * NPART];

// ---------------------------------------------------------------------------
// Prep (single launch): W via 3-term Neumann/Horner series
// (reg*||Minv|| ~ 5e-3 -> truncation (eps*M)^3 ~ 1e-7 relative, far below
// tolerance). One CTA, 1024 threads, intermediates in padded smem.
// ---------------------------------------------------------------------------
__global__ void __launch_bounds__(1024)
prep_W_fused(const float* __restrict__ Minv) {
    __shared__ float A[64 * WSTR];
    __shared__ float B[64 * WSTR];
    const int tid = threadIdx.x;

    // A = I - reg*M
    for (int idx = tid; idx < 4096; idx += 1024) {
        int r = idx >> 6, c = idx & 63;
        A[r * WSTR + c] = ((r == c) ? 1.f : 0.f) - REG * Minv[idx];
    }
    __syncthreads();
    // B = I - reg*M@A
    for (int idx = tid; idx < 4096; idx += 1024) {
        int r = idx >> 6, c = idx & 63;
        float acc = 0.f;
        #pragma unroll 8
        for (int b2 = 0; b2 < 64; b2++) acc += Minv[r * 64 + b2] * A[b2 * WSTR + c];
        B[r * WSTR + c] = ((r == c) ? 1.f : 0.f) - REG * acc;
    }
    __syncthreads();
    // g_W = M@B
    for (int idx = tid; idx < 4096; idx += 1024) {
        int r = idx >> 6, c = idx & 63;
        float acc = 0.f;
        #pragma unroll 8
        for (int b2 = 0; b2 < 64; b2++) acc += Minv[r * 64 + b2] * B[b2 * WSTR + c];
        g_W[idx] = acc;
    }
}

// ---------------------------------------------------------------------------
// Kernel B: one CTA (256 threads) per batch element.
// Exact reduction of the 256x256 KKT to a SYMMETRIC 64x64 system A = reg*D -
// J W J^T in (lambda_n, u). Unpivoted blocked LU (stable here: A is ND away
// from duplicate-contact null directions, and those eliminate benignly with
// O(reg) pivot over O(reg) row). Panel-4 in registers by warp 0 while warps
// 1-4 snapshot the pivot rows concurrently; 2 barriers/panel, 16 panels.
// ---------------------------------------------------------------------------
__global__ void __launch_bounds__(256)
solve_batch_kernel(const float* __restrict__ x, const float* __restrict__ v,
                   const int* __restrict__ cld, const float* __restrict__ dist,
                   const float* __restrict__ mu, const float* __restrict__ cor,
                   float* __restrict__ out) {
    __shared__ float S[NR * STR];         // 64*68*4 = 17408 B; W overlay 64*65
    __shared__ float kappa[NC][NC];       // reused: pivot-row scratch, then gacc
    __shared__ float en[NC][2], et[NC][2];
    __shared__ int   ii[NC], jj[NC];
    __shared__ float hs[NC];
    __shared__ float vs[NPART][2];
    __shared__ float ys[NPART][2];        // reused as sol
    __shared__ float coef[6];             // c10,c20,c21,c30,c31,c32

    float* Wsm     = S;                   // 64*65 = 4160 floats <= 4352
    float* sol     = &ys[0][0];
    float* gacc    = &kappa[0][0];
    float* scratch = &kappa[0][0];        // 4 x 68 floats = 1088 B (< 4 KB)

    const int b    = blockIdx.x;
    const int tid  = threadIdx.x;
    const int r    = tid & 63;            // row 0..63
    const int qt   = tid >> 6;            // column quarter 0..3
    const float* xb = x + b * ND;
    const float* vb = v + b * ND;

    // ---- stage W into smem (coalesced) + load + per-contact geometry ------
    for (int idx = tid; idx < 4096; idx += 256)
        Wsm[(idx >> 6) * WSTR + (idx & 63)] = g_W[idx];
    if (tid < 128) {
        out[b * 256 + tid] = xb[tid];            // x passes through unchanged
        vs[tid >> 1][tid & 1] = vb[tid];
    }
    if (tid < NC) {
        int c = tid;
        int i = cld[b * (NC * 2) + c * 2 + 0];
        int j = cld[b * (NC * 2) + c * 2 + 1];
        ii[c] = i; jj[c] = j;
        float dx = xb[j * 2 + 0] - xb[i * 2 + 0];
        float dy = xb[j * 2 + 1] - xb[i * 2 + 1];
        float inv = rsqrtf(dx * dx + dy * dy);
        float ex = dx * inv, ey = dy * inv;
        en[c][0] = ex;  en[c][1] = ey;
        et[c][0] = -ey; et[c][1] = ex;
        float jv = ex * (vb[j * 2] - vb[i * 2]) + ey * (vb[j * 2 + 1] - vb[i * 2 + 1]);
        hs[c] = fminf(dist[b * NC + c] * 12.5f, cor[b * NC + c] * jv);  // dist/(DT*8)
    }
    __syncthreads();

    // ---- kappa[cr][cs] from smem W ----------------------------------------
    for (int idx = tid; idx < NC * NC; idx += 256) {
        int cr = idx >> 5, cs = idx & 31;
        int ir = ii[cr], jr = jj[cr], is = ii[cs], js = jj[cs];
        kappa[cr][cs] = Wsm[ir * WSTR + is] - Wsm[ir * WSTR + js]
                      - Wsm[jr * WSTR + is] + Wsm[jr * WSTR + js];
    }

    // ---- y = -v + reg * (W v)  (smem W, conflict-free) ---------------------
    if (tid < 128) {
        int p = tid >> 1, s2 = tid & 1;
        float acc = 0.f;
        #pragma unroll 8
        for (int q = 0; q < 64; q++) acc += Wsm[p * WSTR + q] * vs[q][s2];
        ys[p][s2] = -vs[p][s2] + REG * acc;
    }
    __syncthreads();       // all Wsm reads done before S build overwrites

    // ---- build reduced 64x64 system, rhs at col 64 (overwrites Wsm) --------
    {
        const int cr = r & 31;
        const float drx = (r < 32) ? en[cr][0] : et[cr][0];
        const float dry = (r < 32) ? en[cr][1] : et[cr][1];
        for (int c = qt; c < STR; c += 4) {
            float val;
            if (c < 64) {
                int cs = c & 31;
                float dsx = (c < 32) ? en[cs][0] : et[cs][0];
                float dsy = (c < 32) ? en[cs][1] : et[cs][1];
                val = -(drx * dsx + dry * dsy) * kappa[cr][cs];
                if (c == r) val += (r < 32) ? REG : (0.5f * REG);
            } else if (c == 64) {
                float dx = ys[jj[cr]][0] - ys[ii[cr]][0];
                float dy = ys[jj[cr]][1] - ys[ii[cr]][1];
                val = -(drx * dx + dry * dy);
                if (r < 32) val -= hs[r];
            } else {
                val = 0.f;                                        // pad cols
            }
            S[r * STR + c] = val;
        }
    }

    // ---- unpivoted blocked LU: in-register panel + rank-4 update -----------
    for (int k0 = 0; k0 < NR; k0 += 4) {
        __syncthreads();       // (1) previous trailing update / build complete

        const int  kh     = (k0 >= 32);            // panel half (never straddles)
        const int  cstart = (k0 >> 2) + 1;         // first trailing chunk

        // ===== warp 0: panel factorization in registers (no pivoting) ======
        if (tid < 32) {
            const int lane = tid;
            float4 pv0, pv1;
            if (!kh) pv0 = *(const float4*)(S + lane * STR + k0);
            pv1 = *(const float4*)(S + (lane + 32) * STR + k0);

            #pragma unroll
            for (int t = 0; t < 4; t++) {
                const int k  = k0 + t;
                const int kl = k & 31;
                float4 sel = kh ? pv1 : pv0;
                float4 pr4;
                pr4.x = __shfl_sync(0xffffffffu, sel.x, kl);
                pr4.y = __shfl_sync(0xffffffffu, sel.y, kl);
                pr4.z = __shfl_sync(0xffffffffu, sel.z, kl);
                pr4.w = __shfl_sync(0xffffffffu, sel.w, kl);
                float pd   = (t == 0) ? pr4.x : (t == 1) ? pr4.y
                           : (t == 2) ? pr4.z : pr4.w;
                float pinv = 1.f / pd;
                if (!kh && lane > k) {             // rows lane (first half)
                    if (t == 0) {
                        float m = pv0.x * pinv; pv0.x = m;
                        pv0.y -= m * pr4.y; pv0.z -= m * pr4.z; pv0.w -= m * pr4.w;
                    } else if (t == 1) {
                        float m = pv0.y * pinv; pv0.y = m;
                        pv0.z -= m * pr4.z; pv0.w -= m * pr4.w;
                    } else if (t == 2) {
                        float m = pv0.z * pinv; pv0.z = m;
                        pv0.w -= m * pr4.w;
                    } else {
                        float m = pv0.w * pinv; pv0.w = m;
                    }
                }
                if (lane + 32 > k) {               // rows lane+32
                    if (t == 0) {
                        float m = pv1.x * pinv; pv1.x = m;
                        pv1.y -= m * pr4.y; pv1.z -= m * pr4.z; pv1.w -= m * pr4.w;
                    } else if (t == 1) {
                        float m = pv1.y * pinv; pv1.y = m;
                        pv1.z -= m * pr4.z; pv1.w -= m * pr4.w;
                    } else if (t == 2) {
                        float m = pv1.z * pinv; pv1.z = m;
                        pv1.w -= m * pr4.w;
                    } else {
                        float m = pv1.w * pinv; pv1.w = m;
                    }
                }
            }

            if (!kh) *(float4*)(S + lane * STR + k0) = pv0;
            *(float4*)(S + (lane + 32) * STR + k0) = pv1;

            // compose pivot-row correction coefficients (rows k0+1..k0+3)
            {
                float4 selh = kh ? pv1 : pv0;
                const int l1 = (k0 + 1) & 31, l2 = (k0 + 2) & 31, l3 = (k0 + 3) & 31;
                float m10 = __shfl_sync(0xffffffffu, selh.x, l1);
                float m20 = __shfl_sync(0xffffffffu, selh.x, l2);
                float m21 = __shfl_sync(0xffffffffu, selh.y, l2);
                float m30 = __shfl_sync(0xffffffffu, selh.x, l3);
                float m31 = __shfl_sync(0xffffffffu, selh.y, l3);
                float m32 = __shfl_sync(0xffffffffu, selh.z, l3);
                if (lane == 0) {
                    float c10 = -m10;
                    float c21 = -m21;
                    float c20 = -m20 + m21 * m10;
                    float c32 = -m32;
                    float c31 = -m31 + m32 * m21;
                    float c30 = -m30 + m31 * m10 - m32 * c20;
                    coef[0] = c10; coef[1] = c20; coef[2] = c21;
                    coef[3] = c30; coef[4] = c31; coef[5] = c32;
                }
            }
        }
        // ===== warps 1-4: snapshot original pivot rows (concurrent, =========
        // disjoint columns from warp 0's panel chunk)
        else if (tid < 160) {
            int t    = (tid >> 5) - 1;             // 0..3
            int lane = tid & 31;
            int cc   = cstart + lane;
            if (cc <= 16)
                *(float4*)(scratch + t * STR + 4 * cc) =
                    *(const float4*)(S + (k0 + t) * STR + 4 * cc);
        }
        __syncthreads();       // (2) panel, coef, scratch all visible

        // ===== per-row composed coefficients + rank-4 trailing update =======
        if (r > k0) {
            float e0, e1, e2, e3;
            if (r > k0 + 3) {                       // active row
                float4 m = *(const float4*)(S + r * STR + k0);
                e0 = m.x + m.y * coef[0] + m.z * coef[1] + m.w * coef[3];
                e1 = m.y + m.z * coef[2] + m.w * coef[4];
                e2 = m.z + m.w * coef[5];
                e3 = m.w;
            } else if (r == k0 + 1) {
                e0 = -coef[0]; e1 = 0.f; e2 = 0.f; e3 = 0.f;
            } else if (r == k0 + 2) {
                e0 = -coef[1]; e1 = -coef[2]; e2 = 0.f; e3 = 0.f;
            } else {                                // r == k0 + 3
                e0 = -coef[3]; e1 = -coef[4]; e2 = -coef[5]; e3 = 0.f;
            }
            float* Sr = S + r * STR;
            const float* P0 = scratch + 0 * STR;
            const float* P1 = scratch + 1 * STR;
            const float* P2 = scratch + 2 * STR;
            const float* P3 = scratch + 3 * STR;
            for (int c = cstart + qt; c <= 16; c += 4) {
                float4 s  = *(const float4*)(Sr + 4 * c);
                float4 p0 = *(const float4*)(P0 + 4 * c);
                float4 p1 = *(const float4*)(P1 + 4 * c);
                float4 p2 = *(const float4*)(P2 + 4 * c);
                float4 p3 = *(const float4*)(P3 + 4 * c);
                s.x -= e0 * p0.x + e1 * p1.x + e2 * p2.x + e3 * p3.x;
                s.y -= e0 * p0.y + e1 * p1.y + e2 * p2.y + e3 * p3.y;
                s.z -= e0 * p0.z + e1 * p1.z + e2 * p2.z + e3 * p3.z;
                s.w -= e0 * p0.w + e1 * p1.w + e2 * p2.w + e3 * p3.w;
                *(float4*)(Sr + 4 * c) = s;
            }
        }
    }
    __syncthreads();

    // ---- back substitution (warp 0, no block barriers) ---------------------
    if (tid < 32) {
        for (int k = NR - 1; k >= 0; k--) {
            int src = k & 31;
            int pk  = k;
            float cand = S[pk * STR + 64] / S[pk * STR + k];
            float lk = __shfl_sync(0xffffffffu, cand, src);
            if (tid == src && ((k >= 32) == (pk >= 32))) {}
            if (tid == src) sol[k] = lk;   // note: both halves use lane k&31
            if (tid      < k) S[tid * STR + 64]        -= S[tid * STR + k]        * lk;
            if (tid + 32 < k) S[(tid + 32) * STR + 64] -= S[(tid + 32) * STR + k] * lk;
            __syncwarp();
        }
    }
    __syncthreads();

    // ---- reload W (S region dead) + g = G^T l scatter -----------------------
    for (int idx = tid; idx < 4096; idx += 256)
        Wsm[(idx >> 6) * WSTR + (idx & 63)] = g_W[idx];
    if (tid < 128) gacc[tid] = 0.f;
    __syncthreads();
    if (tid < NC) {
        int c = tid;
        float wn = sol[c];                 // lambda_n
        float wt = sol[NC + c];            // u = lambda+ - lambda-
        float wx = wn * en[c][0] + wt * et[c][0];
        float wy = wn * en[c][1] + wt * et[c][1];
        atomicAdd(&gacc[ii[c] * 2 + 0], -wx);
        atomicAdd(&gacc[ii[c] * 2 + 1], -wy);
        atomicAdd(&gacc[jj[c] * 2 + 0],  wx);
        atomicAdd(&gacc[jj[c] * 2 + 1],  wy);
    }
    __syncthreads();

    // ---- v_plus = v + W (g - reg*v)  (smem W) -------------------------------
    if (tid < 128) {
        int p = tid >> 1, s2 = tid & 1;
        float acc = 0.f;
        #pragma unroll 8
        for (int q = 0; q < 64; q++)
            acc += Wsm[p * WSTR + q] * (gacc[q * 2 + s2] - REG * vs[q][s2]);
        out[b * 256 + 128 + tid] = vs[p][s2] + acc;
    }
}

// ---------------------------------------------------------------------------
extern "C" void kernel_launch(void* const* d_in, const int* in_sizes, int n_in,
                              void* d_out, int out_size) {
    const float* x    = (const float*)d_in[0];
    const float* v    = (const float*)d_in[1];
    const int*   cld  = (const int*)  d_in[2];
    const float* dist = (const float*)d_in[3];
    const float* mu   = (const float*)d_in[4];
    const float* cor  = (const float*)d_in[5];
    const float* Minv = (const float*)d_in[6];
    float* out = (float*)d_out;

    int bs = out_size / 256;

    prep_W_fused<<<1, 1024>>>(Minv);
    solve_batch_kernel<<<bs, 256>>>(x, v, cld, dist, mu, cor, out);
}

// round 14
// speedup vs baseline: 14.2504x; 1.7512x over previous
#include <cuda_runtime.h>

// Problem constants (from reference): bs=1024, n=64, d=2, nc=32
#define NPART 64
#define ND    128          // n*d
#define NC    32
#define NR    64           // reduced system size: nc normal + nc tangent-diff
#define REG   1e-3f
#define STR   68           // padded row stride (floats): 64 cols + rhs + 3 pad
#define WSTR  65           // smem W stride (conflict-free padding)

// Precomputed W = (Minv^{-1} + reg I)^{-1} Minv ~= M - reg*M^2  (64x64)
__device__ float g_W[NPART * NPART];

// ---------------------------------------------------------------------------
// Prep: 2-term Neumann, W = M - reg*M@M. Truncation (reg*lam)^2 ~ 2.5e-5
// relative — well under the 1e-3 threshold. 16 CTAs, one element each.
// ---------------------------------------------------------------------------
__global__ void prep_W2(const float* __restrict__ Minv) {
    int idx = blockIdx.x * 256 + threadIdx.x;
    int r = idx >> 6, c = idx & 63;
    float acc = 0.f;
    #pragma unroll 8
    for (int b2 = 0; b2 < 64; b2++) acc += Minv[r * 64 + b2] * Minv[b2 * 64 + c];
    g_W[idx] = Minv[idx] - REG * acc;
}

// ---------------------------------------------------------------------------
// Kernel B: one CTA (256 threads) per batch element.
// Reduced SYMMETRIC 64x64 system solved by unpivoted LDL^T:
//  - warp 0 factorizes the 64x4 panel in registers (as before -> L, d),
//    writes scratchT[t][c] = d_t*L[c,t] (+ forward-solved panel rhs y_t at
//    col 64), all from registers;
//  - trailing update per row r:  A[r,c] -= sum_t L[r,t]*scratchT[t][c]
//    over chunks [cstart .. r>>2] (lower triangle + next panel block) + rhs.
//  No pivot-row snapshot, no coefficient composition. 2 barriers/panel.
// ---------------------------------------------------------------------------
__global__ void __launch_bounds__(256, 7)
solve_batch_kernel(const float* __restrict__ x, const float* __restrict__ v,
                   const int* __restrict__ cld, const float* __restrict__ dist,
                   const float* __restrict__ mu, const float* __restrict__ cor,
                   float* __restrict__ out) {
    __shared__ float S[NR * STR];         // 64*68*4 = 17408 B; W overlay 64*65
    __shared__ float kappa[NC][NC];       // reused: scratchT, then gacc
    __shared__ float en[NC][2], et[NC][2];
    __shared__ int   ii[NC], jj[NC];
    __shared__ float hs[NC];
    __shared__ float vs[NPART][2];
    __shared__ float ys[NPART][2];        // y preserved (v_plus = W g - y)
    __shared__ float sol2[NR];

    float* Wsm      = S;                  // 64*65 = 4160 floats <= 4352
    float* gacc     = &kappa[0][0];
    float* scratchT = &kappa[0][0];       // 4 x 68 floats = 1088 B (< 4 KB)

    const int b    = blockIdx.x;
    const int tid  = threadIdx.x;
    const int r    = tid & 63;            // row 0..63
    const int qt   = tid >> 6;            // column quarter 0..3
    const float* xb = x + b * ND;
    const float* vb = v + b * ND;

    // ---- stage W into smem (coalesced) + load + per-contact geometry ------
    for (int idx = tid; idx < 4096; idx += 256)
        Wsm[(idx >> 6) * WSTR + (idx & 63)] = g_W[idx];
    if (tid < 128) {
        out[b * 256 + tid] = xb[tid];            // x passes through unchanged
        vs[tid >> 1][tid & 1] = vb[tid];
    }
    if (tid < NC) {
        int c = tid;
        int i = cld[b * (NC * 2) + c * 2 + 0];
        int j = cld[b * (NC * 2) + c * 2 + 1];
        ii[c] = i; jj[c] = j;
        float dx = xb[j * 2 + 0] - xb[i * 2 + 0];
        float dy = xb[j * 2 + 1] - xb[i * 2 + 1];
        float inv = rsqrtf(dx * dx + dy * dy);
        float ex = dx * inv, ey = dy * inv;
        en[c][0] = ex;  en[c][1] = ey;
        et[c][0] = -ey; et[c][1] = ex;
        float jv = ex * (vb[j * 2] - vb[i * 2]) + ey * (vb[j * 2 + 1] - vb[i * 2 + 1]);
        hs[c] = fminf(dist[b * NC + c] * 12.5f, cor[b * NC + c] * jv);  // dist/(DT*8)
    }
    __syncthreads();

    // ---- kappa[cr][cs] from smem W ----------------------------------------
    for (int idx = tid; idx < NC * NC; idx += 256) {
        int cr = idx >> 5, cs = idx & 31;
        int ir = ii[cr], jr = jj[cr], is = ii[cs], js = jj[cs];
        kappa[cr][cs] = Wsm[ir * WSTR + is] - Wsm[ir * WSTR + js]
                      - Wsm[jr * WSTR + is] + Wsm[jr * WSTR + js];
    }

    // ---- y = -v + reg * (W v)  (smem W, conflict-free) ---------------------
    if (tid < 128) {
        int p = tid >> 1, s2 = tid & 1;
        float acc = 0.f;
        #pragma unroll 8
        for (int q = 0; q < 64; q++) acc += Wsm[p * WSTR + q] * vs[q][s2];
        ys[p][s2] = -vs[p][s2] + REG * acc;
    }
    __syncthreads();       // all Wsm reads done before S build overwrites

    // ---- build reduced 64x64 system, rhs at col 64 (overwrites Wsm) --------
    {
        const int cr = r & 31;
        const float drx = (r < 32) ? en[cr][0] : et[cr][0];
        const float dry = (r < 32) ? en[cr][1] : et[cr][1];
        for (int c = qt; c < STR; c += 4) {
            float val;
            if (c < 64) {
                int cs = c & 31;
                float dsx = (c < 32) ? en[cs][0] : et[cs][0];
                float dsy = (c < 32) ? en[cs][1] : et[cs][1];
                val = -(drx * dsx + dry * dsy) * kappa[cr][cs];
                if (c == r) val += (r < 32) ? REG : (0.5f * REG);
            } else if (c == 64) {
                float dx = ys[jj[cr]][0] - ys[ii[cr]][0];
                float dy = ys[jj[cr]][1] - ys[ii[cr]][1];
                val = -(drx * dx + dry * dy);
                if (r < 32) val -= hs[r];
            } else {
                val = 0.f;                                        // pad cols
            }
            S[r * STR + c] = val;
        }
    }

    // ---- unpivoted LDL^T: in-register panel + symmetric rank-4 update ------
    for (int k0 = 0; k0 < NR; k0 += 4) {
        __syncthreads();       // (1) previous trailing update / build complete

        const int kh     = (k0 >= 32);             // panel half
        const int cstart = (k0 >> 2) + 1;          // first trailing chunk

        // ===== warp 0: panel factorization + scratchT + rhs forward-solve ==
        if (tid < 32) {
            const int lane = tid;
            float4 pv0, pv1;
            if (!kh) pv0 = *(const float4*)(S + lane * STR + k0);
            pv1 = *(const float4*)(S + (lane + 32) * STR + k0);

            #pragma unroll
            for (int t = 0; t < 4; t++) {
                const int k  = k0 + t;
                const int kl = k & 31;
                float4 sel = kh ? pv1 : pv0;
                float4 pr4;
                pr4.x = __shfl_sync(0xffffffffu, sel.x, kl);
                pr4.y = __shfl_sync(0xffffffffu, sel.y, kl);
                pr4.z = __shfl_sync(0xffffffffu, sel.z, kl);
                pr4.w = __shfl_sync(0xffffffffu, sel.w, kl);
                float pd   = (t == 0) ? pr4.x : (t == 1) ? pr4.y
                           : (t == 2) ? pr4.z : pr4.w;
                float pinv = 1.f / pd;
                if (!kh && lane > k) {
                    if (t == 0) {
                        float m = pv0.x * pinv; pv0.x = m;
                        pv0.y -= m * pr4.y; pv0.z -= m * pr4.z; pv0.w -= m * pr4.w;
                    } else if (t == 1) {
                        float m = pv0.y * pinv; pv0.y = m;
                        pv0.z -= m * pr4.z; pv0.w -= m * pr4.w;
                    } else if (t == 2) {
                        float m = pv0.z * pinv; pv0.z = m;
                        pv0.w -= m * pr4.w;
                    } else {
                        float m = pv0.w * pinv; pv0.w = m;
                    }
                }
                if (lane + 32 > k) {
                    if (t == 0) {
                        float m = pv1.x * pinv; pv1.x = m;
                        pv1.y -= m * pr4.y; pv1.z -= m * pr4.z; pv1.w -= m * pr4.w;
                    } else if (t == 1) {
                        float m = pv1.y * pinv; pv1.y = m;
                        pv1.z -= m * pr4.z; pv1.w -= m * pr4.w;
                    } else if (t == 2) {
                        float m = pv1.z * pinv; pv1.z = m;
                        pv1.w -= m * pr4.w;
                    } else {
                        float m = pv1.w * pinv; pv1.w = m;
                    }
                }
            }

            if (!kh) *(float4*)(S + lane * STR + k0) = pv0;
            *(float4*)(S + (lane + 32) * STR + k0) = pv1;

            // gather panel rows k0..k0+3 (post-factorization): d and m values
            float4 selh = kh ? pv1 : pv0;
            const int l0 = k0 & 31;
            float4 q0, q1, q2, q3;
            q0.x = __shfl_sync(0xffffffffu, selh.x, l0);
            q0.y = __shfl_sync(0xffffffffu, selh.y, l0);
            q0.z = __shfl_sync(0xffffffffu, selh.z, l0);
            q0.w = __shfl_sync(0xffffffffu, selh.w, l0);
            q1.x = __shfl_sync(0xffffffffu, selh.x, l0 + 1);
            q1.y = __shfl_sync(0xffffffffu, selh.y, l0 + 1);
            q1.z = __shfl_sync(0xffffffffu, selh.z, l0 + 1);
            q1.w = __shfl_sync(0xffffffffu, selh.w, l0 + 1);
            q2.x = __shfl_sync(0xffffffffu, selh.x, l0 + 2);
            q2.y = __shfl_sync(0xffffffffu, selh.y, l0 + 2);
            q2.z = __shfl_sync(0xffffffffu, selh.z, l0 + 2);
            q2.w = __shfl_sync(0xffffffffu, selh.w, l0 + 2);
            q3.x = __shfl_sync(0xffffffffu, selh.x, l0 + 3);
            q3.y = __shfl_sync(0xffffffffu, selh.y, l0 + 3);
            q3.z = __shfl_sync(0xffffffffu, selh.z, l0 + 3);
            q3.w = __shfl_sync(0xffffffffu, selh.w, l0 + 3);
            const float d0 = q0.x, d1 = q1.y, d2 = q2.z, d3 = q3.w;

            // scratchT[t][c] = d_t * L[c,t]  (from registers; rows >= k0+4
            // are the only ones ever read)
            if (!kh) {
                scratchT[0 * STR + lane] = d0 * pv0.x;
                scratchT[1 * STR + lane] = d1 * pv0.y;
                scratchT[2 * STR + lane] = d2 * pv0.z;
                scratchT[3 * STR + lane] = d3 * pv0.w;
            }
            scratchT[0 * STR + lane + 32] = d0 * pv1.x;
            scratchT[1 * STR + lane + 32] = d1 * pv1.y;
            scratchT[2 * STR + lane + 32] = d2 * pv1.z;
            scratchT[3 * STR + lane + 32] = d3 * pv1.w;

            // forward-solve panel rhs: y_t = r_t - sum_{s<t} m_ts y_s
            if (lane == 0) {
                float r0 = S[(k0 + 0) * STR + 64];
                float r1 = S[(k0 + 1) * STR + 64];
                float r2 = S[(k0 + 2) * STR + 64];
                float r3 = S[(k0 + 3) * STR + 64];
                float y0 = r0;
                float y1 = r1 - q1.x * y0;
                float y2 = r2 - q2.x * y0 - q2.y * y1;
                float y3 = r3 - q3.x * y0 - q3.y * y1 - q3.z * y2;
                S[(k0 + 1) * STR + 64] = y1;
                S[(k0 + 2) * STR + 64] = y2;
                S[(k0 + 3) * STR + 64] = y3;
                scratchT[0 * STR + 64] = y0;   // rhs column of scratchT
                scratchT[1 * STR + 64] = y1;
                scratchT[2 * STR + 64] = y2;
                scratchT[3 * STR + 64] = y3;
            }
        }
        __syncthreads();       // (2) panel L, scratchT, panel rhs visible

        // ===== symmetric rank-4 trailing update (lower tri + rhs) ===========
        if (r > k0 + 3) {
            float* Sr = S + r * STR;
            float4 m = *(const float4*)(Sr + k0);      // own L[r, k0..k0+3]
            const float* P0 = scratchT + 0 * STR;
            const float* P1 = scratchT + 1 * STR;
            const float* P2 = scratchT + 2 * STR;
            const float* P3 = scratchT + 3 * STR;
            const int cmax = r >> 2;                   // lower-tri chunk limit
            for (int c = cstart + qt; c <= cmax; c += 4) {
                float4 s  = *(const float4*)(Sr + 4 * c);
                float4 p0 = *(const float4*)(P0 + 4 * c);
                float4 p1 = *(const float4*)(P1 + 4 * c);
                float4 p2 = *(const float4*)(P2 + 4 * c);
                float4 p3 = *(const float4*)(P3 + 4 * c);
                s.x -= m.x * p0.x + m.y * p1.x + m.z * p2.x + m.w * p3.x;
                s.y -= m.x * p0.y + m.y * p1.y + m.z * p2.y + m.w * p3.y;
                s.z -= m.x * p0.z + m.y * p1.z + m.z * p2.z + m.w * p3.z;
                s.w -= m.x * p0.w + m.y * p1.w + m.z * p2.w + m.w * p3.w;
                *(float4*)(Sr + 4 * c) = s;
            }
            if (qt == ((16 - cstart) & 3)) {           // rhs chunk (col 64)
                float s64 = Sr[64];
                s64 -= m.x * P0[64] + m.y * P1[64] + m.z * P2[64] + m.w * P3[64];
                Sr[64] = s64;
            }
        }
    }
    __syncthreads();

    // ---- back substitution: w = z/d, then x_k = w_k; w_r -= L[k,r] x_k -----
    if (tid < 64) S[tid * STR + 64] /= S[tid * STR + tid];
    __syncthreads();
    if (tid < 32) {
        for (int k = NR - 1; k >= 0; k--) {
            float xk = S[k * STR + 64];                // broadcast LDS
            if (tid == (k & 31)) sol2[k] = xk;
            if (tid      < k) S[tid * STR + 64]        -= S[k * STR + tid]      * xk;
            if (tid + 32 < k) S[(tid + 32) * STR + 64] -= S[k * STR + tid + 32] * xk;
            __syncwarp();
        }
    }
    __syncthreads();

    // ---- reload W (S region dead) + g = G^T l scatter -----------------------
    for (int idx = tid; idx < 4096; idx += 256)
        Wsm[(idx >> 6) * WSTR + (idx & 63)] = g_W[idx];
    if (tid < 128) gacc[tid] = 0.f;
    __syncthreads();
    if (tid < NC) {
        int c = tid;
        float wn = sol2[c];                // lambda_n
        float wt = sol2[NC + c];           // u = lambda+ - lambda-
        float wx = wn * en[c][0] + wt * et[c][0];
        float wy = wn * en[c][1] + wt * et[c][1];
        atomicAdd(&gacc[ii[c] * 2 + 0], -wx);
        atomicAdd(&gacc[ii[c] * 2 + 1], -wy);
        atomicAdd(&gacc[jj[c] * 2 + 0],  wx);
        atomicAdd(&gacc[jj[c] * 2 + 1],  wy);
    }
    __syncthreads();

    // ---- v_plus = W g - y  (identity: v + W(g - reg v) = Wg - y) -----------
    if (tid < 128) {
        int p = tid >> 1, s2 = tid & 1;
        float acc = 0.f;
        #pragma unroll 8
        for (int q = 0; q < 64; q++)
            acc += Wsm[p * WSTR + q] * gacc[q * 2 + s2];
        out[b * 256 + 128 + tid] = acc - ys[p][s2];
    }
}

// ---------------------------------------------------------------------------
extern "C" void kernel_launch(void* const* d_in, const int* in_sizes, int n_in,
                              void* d_out, int out_size) {
    const float* x    = (const float*)d_in[0];
    const float* v    = (const float*)d_in[1];
    const int*   cld  = (const int*)  d_in[2];
    const float* dist = (const float*)d_in[3];
    const float* mu   = (const float*)d_in[4];
    const float* cor  = (const float*)d_in[5];
    const float* Minv = (const float*)d_in[6];
    float* out = (float*)d_out;

    int bs = out_size / 256;

    prep_W2<<<16, 256>>>(Minv);
    solve_batch_kernel<<<bs, 256>>>(x, v, cld, dist, mu, cor, out);
}

// round 15
// speedup vs baseline: 20.1343x; 1.4129x over previous
#include <cuda_runtime.h>

// Problem constants (from reference): bs=1024, n=64, d=2, nc=32
#define NPART 64
#define ND    128          // n*d
#define NC    32
#define NR    64           // reduced system size: nc normal + nc tangent-diff
#define REG   1e-3f
#define STR   68           // padded row stride (floats): 64 cols + rhs + 3 pad
#define WSTR  65           // smem W stride (conflict-free padding)

// Precomputed W = (Minv^{-1} + reg I)^{-1} Minv ~= M - reg*M^2  (64x64)
__device__ float g_W[NPART * NPART];

// ---------------------------------------------------------------------------
// Prep: 2-term Neumann, W = M - reg*M@M. Truncation (reg*lam)^2 ~ 2.5e-5
// relative — well under the 1e-3 threshold. 16 CTAs, one element each.
// ---------------------------------------------------------------------------
__global__ void prep_W2(const float* __restrict__ Minv) {
    int idx = blockIdx.x * 256 + threadIdx.x;
    int r = idx >> 6, c = idx & 63;
    float acc = 0.f;
    #pragma unroll 8
    for (int b2 = 0; b2 < 64; b2++) acc += Minv[r * 64 + b2] * Minv[b2 * 64 + c];
    g_W[idx] = Minv[idx] - REG * acc;
}

// ---------------------------------------------------------------------------
// Kernel B: one CTA (128 threads) per batch element.
// Reduced SYMMETRIC 64x64 LDL^T, panel width 8:
//  - warp 0 holds the 64x8 panel in registers (2 rows/lane) AND the rhs as a
//    9th register column carried across ALL panels (w -= m*z_t per step);
//    after the last panel warp 0 already holds z and back-substitutes
//    entirely in registers via shuffles (no smem rhs, no syncwarp loops);
//  - trailing rank-8 update per row over chunks [cstart .. 2*(r>>3)+1]
//    (lower triangle extended to the full 8-aligned diagonal block, valid by
//    symmetry of the update formula);
//  - 2 barriers/panel, 8 panels.
// ---------------------------------------------------------------------------
__global__ void __launch_bounds__(128, 8)
solve_batch_kernel(const float* __restrict__ x, const float* __restrict__ v,
                   const int* __restrict__ cld, const float* __restrict__ dist,
                   const float* __restrict__ mu, const float* __restrict__ cor,
                   float* __restrict__ out) {
    __shared__ float S[NR * STR];         // 64*68*4 = 17408 B; W overlay 64*65
    __shared__ float kappa[NC][NC];       // reused: scratchT, then gacc
    __shared__ float en[NC][2], et[NC][2];
    __shared__ int   ii[NC], jj[NC];
    __shared__ float hs[NC];
    __shared__ float vs[NPART][2];
    __shared__ float ys[NPART][2];        // y preserved (v_plus = W g - y)
    __shared__ float sol2[NR];

    float* Wsm      = S;                  // 64*65 = 4160 floats <= 64*68
    float* gacc     = &kappa[0][0];
    float* scratchT = &kappa[0][0];       // 8 x 68 floats = 2176 B (< 4 KB)

    const int b    = blockIdx.x;
    const int tid  = threadIdx.x;
    const int r    = tid & 63;            // row 0..63
    const int qt   = tid >> 6;            // column parity group 0..1
    const float* xb = x + b * ND;
    const float* vb = v + b * ND;

    // ---- stage W into smem (float4 gmem reads) + loads + geometry ----------
    {
        const float4* gW4 = (const float4*)g_W;
        for (int idx = tid; idx < 1024; idx += 128) {
            float4 f = gW4[idx];
            int row = idx >> 4, c4 = (idx & 15) * 4;
            float* w = Wsm + row * WSTR + c4;
            w[0] = f.x; w[1] = f.y; w[2] = f.z; w[3] = f.w;
        }
    }
    out[b * 256 + tid] = xb[tid];                // x passes through unchanged
    vs[tid >> 1][tid & 1] = vb[tid];
    if (tid < NC) {
        int c = tid;
        int i = cld[b * (NC * 2) + c * 2 + 0];
        int j = cld[b * (NC * 2) + c * 2 + 1];
        ii[c] = i; jj[c] = j;
        float dx = xb[j * 2 + 0] - xb[i * 2 + 0];
        float dy = xb[j * 2 + 1] - xb[i * 2 + 1];
        float inv = rsqrtf(dx * dx + dy * dy);
        float ex = dx * inv, ey = dy * inv;
        en[c][0] = ex;  en[c][1] = ey;
        et[c][0] = -ey; et[c][1] = ex;
        float jv = ex * (vb[j * 2] - vb[i * 2]) + ey * (vb[j * 2 + 1] - vb[i * 2 + 1]);
        hs[c] = fminf(dist[b * NC + c] * 12.5f, cor[b * NC + c] * jv);  // dist/(DT*8)
    }
    __syncthreads();

    // ---- kappa[cr][cs] from smem W ----------------------------------------
    for (int idx = tid; idx < NC * NC; idx += 128) {
        int cr = idx >> 5, cs = idx & 31;
        int ir = ii[cr], jr = jj[cr], is = ii[cs], js = jj[cs];
        kappa[cr][cs] = Wsm[ir * WSTR + is] - Wsm[ir * WSTR + js]
                      - Wsm[jr * WSTR + is] + Wsm[jr * WSTR + js];
    }

    // ---- y = -v + reg * (W v) ----------------------------------------------
    {
        int p = tid >> 1, s2 = tid & 1;
        float acc = 0.f;
        #pragma unroll 8
        for (int q = 0; q < 64; q++) acc += Wsm[p * WSTR + q] * vs[q][s2];
        ys[p][s2] = -vs[p][s2] + REG * acc;
    }
    __syncthreads();       // all Wsm reads done before S build overwrites

    // ---- build reduced system (cols <= r|7 and 64 only), rhs at col 64 -----
    {
        const int cr = r & 31;
        const float drx = (r < 32) ? en[cr][0] : et[cr][0];
        const float dry = (r < 32) ? en[cr][1] : et[cr][1];
        const int climit = r | 7;
        for (int c = qt; c < 65; c += 2) {
            if (c > climit && c != 64) continue;
            float val;
            if (c < 64) {
                int cs = c & 31;
                float dsx = (c < 32) ? en[cs][0] : et[cs][0];
                float dsy = (c < 32) ? en[cs][1] : et[cs][1];
                val = -(drx * dsx + dry * dsy) * kappa[cr][cs];
                if (c == r) val += (r < 32) ? REG : (0.5f * REG);
            } else {
                float dx = ys[jj[cr]][0] - ys[ii[cr]][0];
                float dy = ys[jj[cr]][1] - ys[ii[cr]][1];
                val = -(drx * dx + dry * dy);
                if (r < 32) val -= hs[r];
            }
            S[r * STR + c] = val;
        }
    }

    // ---- LDL^T, panel width 8, rhs carried in warp-0 registers -------------
    float w0 = 0.f, w1 = 0.f;             // warp 0 only: rhs registers
    for (int k0 = 0; k0 < NR; k0 += 8) {
        __syncthreads();       // (1) previous trailing update / build complete

        const int kh     = (k0 >= 32);
        const int cstart = (k0 >> 2) + 2;

        if (tid < 32) {
            const int lane = tid;
            if (k0 == 0) {
                w0 = S[lane * STR + 64];
                w1 = S[(lane + 32) * STR + 64];
            }
            float A0[8], A1[8];
            if (!kh) {
                float4 f = *(const float4*)(S + lane * STR + k0);
                A0[0] = f.x; A0[1] = f.y; A0[2] = f.z; A0[3] = f.w;
                f = *(const float4*)(S + lane * STR + k0 + 4);
                A0[4] = f.x; A0[5] = f.y; A0[6] = f.z; A0[7] = f.w;
            }
            {
                float4 f = *(const float4*)(S + (lane + 32) * STR + k0);
                A1[0] = f.x; A1[1] = f.y; A1[2] = f.z; A1[3] = f.w;
                f = *(const float4*)(S + (lane + 32) * STR + k0 + 4);
                A1[4] = f.x; A1[5] = f.y; A1[6] = f.z; A1[7] = f.w;
            }

            #pragma unroll
            for (int t = 0; t < 8; t++) {
                const int k  = k0 + t;
                const int kl = k & 31;
                float pr[8];
                #pragma unroll
                for (int u = 0; u < 8; u++)
                    if (u >= t)
                        pr[u] = __shfl_sync(0xffffffffu, kh ? A1[u] : A0[u], kl);
                float zt   = __shfl_sync(0xffffffffu, kh ? w1 : w0, kl);
                float pinv = __fdividef(1.f, pr[t]);
                if (!kh && lane > k) {
                    float m = A0[t] * pinv; A0[t] = m;
                    #pragma unroll
                    for (int u = t + 1; u < 8; u++) A0[u] -= m * pr[u];
                    w0 -= m * zt;
                }
                if (lane + 32 > k) {
                    float m = A1[t] * pinv; A1[t] = m;
                    #pragma unroll
                    for (int u = t + 1; u < 8; u++) A1[u] -= m * pr[u];
                    w1 -= m * zt;
                }
                // scratchT row t: d_t * L[c,t]  (column t final after step t)
                if (!kh) scratchT[t * STR + lane] = pr[t] * A0[t];
                scratchT[t * STR + lane + 32] = pr[t] * A1[t];
            }

            // write back panel (rows >= k0 only)
            if (!kh && lane >= k0) {
                float4 f; f.x = A0[0]; f.y = A0[1]; f.z = A0[2]; f.w = A0[3];
                *(float4*)(S + lane * STR + k0) = f;
                f.x = A0[4]; f.y = A0[5]; f.z = A0[6]; f.w = A0[7];
                *(float4*)(S + lane * STR + k0 + 4) = f;
            }
            if (lane + 32 >= k0) {
                float4 f; f.x = A1[0]; f.y = A1[1]; f.z = A1[2]; f.w = A1[3];
                *(float4*)(S + (lane + 32) * STR + k0) = f;
                f.x = A1[4]; f.y = A1[5]; f.z = A1[6]; f.w = A1[7];
                *(float4*)(S + (lane + 32) * STR + k0 + 4) = f;
            }
        }
        __syncthreads();       // (2) panel L + scratchT visible

        // ===== rank-8 trailing update (lower tri + 8-block mirror) ==========
        if (r >= k0 + 8) {
            float* Sr = S + r * STR;
            float4 ma = *(const float4*)(Sr + k0);
            float4 mb = *(const float4*)(Sr + k0 + 4);
            const int cmax = 2 * (r >> 3) + 1;
            for (int c = cstart + qt; c <= cmax; c += 2) {
                float4 s  = *(const float4*)(Sr + 4 * c);
                float4 p0 = *(const float4*)(scratchT + 0 * STR + 4 * c);
                float4 p1 = *(const float4*)(scratchT + 1 * STR + 4 * c);
                float4 p2 = *(const float4*)(scratchT + 2 * STR + 4 * c);
                float4 p3 = *(const float4*)(scratchT + 3 * STR + 4 * c);
                float4 p4 = *(const float4*)(scratchT + 4 * STR + 4 * c);
                float4 p5 = *(const float4*)(scratchT + 5 * STR + 4 * c);
                float4 p6 = *(const float4*)(scratchT + 6 * STR + 4 * c);
                float4 p7 = *(const float4*)(scratchT + 7 * STR + 4 * c);
                s.x -= ma.x * p0.x + ma.y * p1.x + ma.z * p2.x + ma.w * p3.x
                     + mb.x * p4.x + mb.y * p5.x + mb.z * p6.x + mb.w * p7.x;
                s.y -= ma.x * p0.y + ma.y * p1.y + ma.z * p2.y + ma.w * p3.y
                     + mb.x * p4.y + mb.y * p5.y + mb.z * p6.y + mb.w * p7.y;
                s.z -= ma.x * p0.z + ma.y * p1.z + ma.z * p2.z + ma.w * p3.z
                     + mb.x * p4.z + mb.y * p5.z + mb.z * p6.z + mb.w * p7.z;
                s.w -= ma.x * p0.w + ma.y * p1.w + ma.z * p2.w + ma.w * p3.w
                     + mb.x * p4.w + mb.y * p5.w + mb.z * p6.w + mb.w * p7.w;
                *(float4*)(Sr + 4 * c) = s;
            }
        }
    }
    __syncthreads();

    // ---- back substitution, warp 0, all in registers ------------------------
    // solve L^T x = D^{-1} z :  x_r = z_r/d_r - sum_{k>r} L[k,r]*x_k
    if (tid < 32) {
        const int lane = tid;
        w0 = __fdividef(w0, S[lane * STR + lane]);
        w1 = __fdividef(w1, S[(lane + 32) * STR + (lane + 32)]);
        for (int k = NR - 1; k > 0; k--) {
            float xk = (k >= 32) ? __shfl_sync(0xffffffffu, w1, k - 32)
                                 : __shfl_sync(0xffffffffu, w0, k);
            const float* Lk = S + k * STR;
            if (lane < k)      w0 -= Lk[lane] * xk;
            if (lane + 32 < k) w1 -= Lk[lane + 32] * xk;
        }
        sol2[lane]      = w0;
        sol2[lane + 32] = w1;
    }
    __syncthreads();

    // ---- reload W (S region dead) + g = G^T l scatter -----------------------
    {
        const float4* gW4 = (const float4*)g_W;
        for (int idx = tid; idx < 1024; idx += 128) {
            float4 f = gW4[idx];
            int row = idx >> 4, c4 = (idx & 15) * 4;
            float* w = Wsm + row * WSTR + c4;
            w[0] = f.x; w[1] = f.y; w[2] = f.z; w[3] = f.w;
        }
    }
    gacc[tid] = 0.f;
    __syncthreads();
    if (tid < NC) {
        int c = tid;
        float wn = sol2[c];                // lambda_n
        float wt = sol2[NC + c];           // u = lambda+ - lambda-
        float wx = wn * en[c][0] + wt * et[c][0];
        float wy = wn * en[c][1] + wt * et[c][1];
        atomicAdd(&gacc[ii[c] * 2 + 0], -wx);
        atomicAdd(&gacc[ii[c] * 2 + 1], -wy);
        atomicAdd(&gacc[jj[c] * 2 + 0],  wx);
        atomicAdd(&gacc[jj[c] * 2 + 1],  wy);
    }
    __syncthreads();

    // ---- v_plus = W g - y  (identity: v + W(g - reg v) = Wg - y) -----------
    {
        int p = tid >> 1, s2 = tid & 1;
        float acc = 0.f;
        #pragma unroll 8
        for (int q = 0; q < 64; q++)
            acc += Wsm[p * WSTR + q] * gacc[q * 2 + s2];
        out[b * 256 + 128 + tid] = acc - ys[p][s2];
    }
}

// ---------------------------------------------------------------------------
extern "C" void kernel_launch(void* const* d_in, const int* in_sizes, int n_in,
                              void* d_out, int out_size) {
    const float* x    = (const float*)d_in[0];
    const float* v    = (const float*)d_in[1];
    const int*   cld  = (const int*)  d_in[2];
    const float* dist = (const float*)d_in[3];
    const float* mu   = (const float*)d_in[4];
    const float* cor  = (const float*)d_in[5];
    const float* Minv = (const float*)d_in[6];
    float* out = (float*)d_out;

    int bs = out_size / 256;

    prep_W2<<<16, 256>>>(Minv);
    solve_batch_kernel<<<bs, 128>>>(x, v, cld, dist, mu, cor, out);
}

// round 16
// speedup vs baseline: 20.2587x; 1.0062x over previous
#include <cuda_runtime.h>

// Problem constants (from reference): bs=1024, n=64, d=2, nc=32
#define NPART 64
#define ND    128          // n*d
#define NC    32
#define NR    64           // reduced system size: nc normal + nc tangent-diff
#define REG   1e-3f
#define STR   68           // padded row stride (floats): 64 cols + rhs + 3 pad
#define WSTR  65           // smem W stride (conflict-free padding)

// Precomputed W = (Minv^{-1} + reg I)^{-1} Minv ~= M - reg*M^2  (64x64)
__device__ float g_W[NPART * NPART];

// ---------------------------------------------------------------------------
// Prep: 2-term Neumann, W = M - reg*M@M. Truncation (reg*lam)^2 ~ 2.5e-5
// relative — well under the 1e-3 threshold. 16 CTAs, one element each.
// ---------------------------------------------------------------------------
__global__ void prep_W2(const float* __restrict__ Minv) {
    int idx = blockIdx.x * 256 + threadIdx.x;
    int r = idx >> 6, c = idx & 63;
    float acc = 0.f;
    #pragma unroll 8
    for (int b2 = 0; b2 < 64; b2++) acc += Minv[r * 64 + b2] * Minv[b2 * 64 + c];
    g_W[idx] = Minv[idx] - REG * acc;
}

// ---------------------------------------------------------------------------
// Kernel B: one CTA (128 threads) per batch element.
// Reduced SYMMETRIC 64x64 LDL^T, panel width 8:
//  - warp 0 holds the 64x8 panel in registers (2 rows/lane) AND the rhs as a
//    9th register column carried across ALL panels (w -= m*z_t per step);
//    after the last panel warp 0 already holds z and back-substitutes
//    entirely in registers via shuffles (no smem rhs, no syncwarp loops);
//  - trailing rank-8 update per row over chunks [cstart .. 2*(r>>3)+1]
//    (lower triangle extended to the full 8-aligned diagonal block, valid by
//    symmetry of the update formula);
//  - 2 barriers/panel, 8 panels.
// ---------------------------------------------------------------------------
__global__ void __launch_bounds__(128, 8)
solve_batch_kernel(const float* __restrict__ x, const float* __restrict__ v,
                   const int* __restrict__ cld, const float* __restrict__ dist,
                   const float* __restrict__ mu, const float* __restrict__ cor,
                   float* __restrict__ out) {
    __shared__ float S[NR * STR];         // 64*68*4 = 17408 B; W overlay 64*65
    __shared__ float kappa[NC][NC];       // reused: scratchT, then gacc
    __shared__ float en[NC][2], et[NC][2];
    __shared__ int   ii[NC], jj[NC];
    __shared__ float hs[NC];
    __shared__ float vs[NPART][2];
    __shared__ float ys[NPART][2];        // y preserved (v_plus = W g - y)
    __shared__ float sol2[NR];

    float* Wsm      = S;                  // 64*65 = 4160 floats <= 64*68
    float* gacc     = &kappa[0][0];
    float* scratchT = &kappa[0][0];       // 8 x 68 floats = 2176 B (< 4 KB)

    const int b    = blockIdx.x;
    const int tid  = threadIdx.x;
    const int r    = tid & 63;            // row 0..63
    const int qt   = tid >> 6;            // column parity group 0..1
    const float* xb = x + b * ND;
    const float* vb = v + b * ND;

    // ---- stage W into smem (float4 gmem reads) + loads + geometry ----------
    {
        const float4* gW4 = (const float4*)g_W;
        for (int idx = tid; idx < 1024; idx += 128) {
            float4 f = gW4[idx];
            int row = idx >> 4, c4 = (idx & 15) * 4;
            float* w = Wsm + row * WSTR + c4;
            w[0] = f.x; w[1] = f.y; w[2] = f.z; w[3] = f.w;
        }
    }
    out[b * 256 + tid] = xb[tid];                // x passes through unchanged
    vs[tid >> 1][tid & 1] = vb[tid];
    if (tid < NC) {
        int c = tid;
        int i = cld[b * (NC * 2) + c * 2 + 0];
        int j = cld[b * (NC * 2) + c * 2 + 1];
        ii[c] = i; jj[c] = j;
        float dx = xb[j * 2 + 0] - xb[i * 2 + 0];
        float dy = xb[j * 2 + 1] - xb[i * 2 + 1];
        float inv = rsqrtf(dx * dx + dy * dy);
        float ex = dx * inv, ey = dy * inv;
        en[c][0] = ex;  en[c][1] = ey;
        et[c][0] = -ey; et[c][1] = ex;
        float jv = ex * (vb[j * 2] - vb[i * 2]) + ey * (vb[j * 2 + 1] - vb[i * 2 + 1]);
        hs[c] = fminf(dist[b * NC + c] * 12.5f, cor[b * NC + c] * jv);  // dist/(DT*8)
    }
    __syncthreads();

    // ---- kappa[cr][cs] from smem W ----------------------------------------
    for (int idx = tid; idx < NC * NC; idx += 128) {
        int cr = idx >> 5, cs = idx & 31;
        int ir = ii[cr], jr = jj[cr], is = ii[cs], js = jj[cs];
        kappa[cr][cs] = Wsm[ir * WSTR + is] - Wsm[ir * WSTR + js]
                      - Wsm[jr * WSTR + is] + Wsm[jr * WSTR + js];
    }

    // ---- y = -v + reg * (W v) ----------------------------------------------
    {
        int p = tid >> 1, s2 = tid & 1;
        float acc = 0.f;
        #pragma unroll 8
        for (int q = 0; q < 64; q++) acc += Wsm[p * WSTR + q] * vs[q][s2];
        ys[p][s2] = -vs[p][s2] + REG * acc;
    }
    __syncthreads();       // all Wsm reads done before S build overwrites

    // ---- build reduced system (cols <= r|7 and 64 only), rhs at col 64 -----
    {
        const int cr = r & 31;
        const float drx = (r < 32) ? en[cr][0] : et[cr][0];
        const float dry = (r < 32) ? en[cr][1] : et[cr][1];
        const int climit = r | 7;
        for (int c = qt; c < 65; c += 2) {
            if (c > climit && c != 64) continue;
            float val;
            if (c < 64) {
                int cs = c & 31;
                float dsx = (c < 32) ? en[cs][0] : et[cs][0];
                float dsy = (c < 32) ? en[cs][1] : et[cs][1];
                val = -(drx * dsx + dry * dsy) * kappa[cr][cs];
                if (c == r) val += (r < 32) ? REG : (0.5f * REG);
            } else {
                float dx = ys[jj[cr]][0] - ys[ii[cr]][0];
                float dy = ys[jj[cr]][1] - ys[ii[cr]][1];
                val = -(drx * dx + dry * dy);
                if (r < 32) val -= hs[r];
            }
            S[r * STR + c] = val;
        }
    }

    // ---- LDL^T, panel width 8, rhs carried in warp-0 registers -------------
    float w0 = 0.f, w1 = 0.f;             // warp 0 only: rhs registers
    for (int k0 = 0; k0 < NR; k0 += 8) {
        __syncthreads();       // (1) previous trailing update / build complete

        const int kh     = (k0 >= 32);
        const int cstart = (k0 >> 2) + 2;

        if (tid < 32) {
            const int lane = tid;
            if (k0 == 0) {
                w0 = S[lane * STR + 64];
                w1 = S[(lane + 32) * STR + 64];
            }
            float A0[8], A1[8];
            if (!kh) {
                float4 f = *(const float4*)(S + lane * STR + k0);
                A0[0] = f.x; A0[1] = f.y; A0[2] = f.z; A0[3] = f.w;
                f = *(const float4*)(S + lane * STR + k0 + 4);
                A0[4] = f.x; A0[5] = f.y; A0[6] = f.z; A0[7] = f.w;
            }
            {
                float4 f = *(const float4*)(S + (lane + 32) * STR + k0);
                A1[0] = f.x; A1[1] = f.y; A1[2] = f.z; A1[3] = f.w;
                f = *(const float4*)(S + (lane + 32) * STR + k0 + 4);
                A1[4] = f.x; A1[5] = f.y; A1[6] = f.z; A1[7] = f.w;
            }

            #pragma unroll
            for (int t = 0; t < 8; t++) {
                const int k  = k0 + t;
                const int kl = k & 31;
                float pr[8];
                #pragma unroll
                for (int u = 0; u < 8; u++)
                    if (u >= t)
                        pr[u] = __shfl_sync(0xffffffffu, kh ? A1[u] : A0[u], kl);
                float zt   = __shfl_sync(0xffffffffu, kh ? w1 : w0, kl);
                float pinv = __fdividef(1.f, pr[t]);
                if (!kh && lane > k) {
                    float m = A0[t] * pinv; A0[t] = m;
                    #pragma unroll
                    for (int u = t + 1; u < 8; u++) A0[u] -= m * pr[u];
                    w0 -= m * zt;
                }
                if (lane + 32 > k) {
                    float m = A1[t] * pinv; A1[t] = m;
                    #pragma unroll
                    for (int u = t + 1; u < 8; u++) A1[u] -= m * pr[u];
                    w1 -= m * zt;
                }
                // scratchT row t: d_t * L[c,t]  (column t final after step t)
                if (!kh) scratchT[t * STR + lane] = pr[t] * A0[t];
                scratchT[t * STR + lane + 32] = pr[t] * A1[t];
            }

            // write back panel (rows >= k0 only)
            if (!kh && lane >= k0) {
                float4 f; f.x = A0[0]; f.y = A0[1]; f.z = A0[2]; f.w = A0[3];
                *(float4*)(S + lane * STR + k0) = f;
                f.x = A0[4]; f.y = A0[5]; f.z = A0[6]; f.w = A0[7];
                *(float4*)(S + lane * STR + k0 + 4) = f;
            }
            if (lane + 32 >= k0) {
                float4 f; f.x = A1[0]; f.y = A1[1]; f.z = A1[2]; f.w = A1[3];
                *(float4*)(S + (lane + 32) * STR + k0) = f;
                f.x = A1[4]; f.y = A1[5]; f.z = A1[6]; f.w = A1[7];
                *(float4*)(S + (lane + 32) * STR + k0 + 4) = f;
            }
        }
        __syncthreads();       // (2) panel L + scratchT visible

        // ===== rank-8 trailing update (lower tri + 8-block mirror) ==========
        if (r >= k0 + 8) {
            float* Sr = S + r * STR;
            float4 ma = *(const float4*)(Sr + k0);
            float4 mb = *(const float4*)(Sr + k0 + 4);
            const int cmax = 2 * (r >> 3) + 1;
            for (int c = cstart + qt; c <= cmax; c += 2) {
                float4 s  = *(const float4*)(Sr + 4 * c);
                float4 p0 = *(const float4*)(scratchT + 0 * STR + 4 * c);
                float4 p1 = *(const float4*)(scratchT + 1 * STR + 4 * c);
                float4 p2 = *(const float4*)(scratchT + 2 * STR + 4 * c);
                float4 p3 = *(const float4*)(scratchT + 3 * STR + 4 * c);
                float4 p4 = *(const float4*)(scratchT + 4 * STR + 4 * c);
                float4 p5 = *(const float4*)(scratchT + 5 * STR + 4 * c);
                float4 p6 = *(const float4*)(scratchT + 6 * STR + 4 * c);
                float4 p7 = *(const float4*)(scratchT + 7 * STR + 4 * c);
                s.x -= ma.x * p0.x + ma.y * p1.x + ma.z * p2.x + ma.w * p3.x
                     + mb.x * p4.x + mb.y * p5.x + mb.z * p6.x + mb.w * p7.x;
                s.y -= ma.x * p0.y + ma.y * p1.y + ma.z * p2.y + ma.w * p3.y
                     + mb.x * p4.y + mb.y * p5.y + mb.z * p6.y + mb.w * p7.y;
                s.z -= ma.x * p0.z + ma.y * p1.z + ma.z * p2.z + ma.w * p3.z
                     + mb.x * p4.z + mb.y * p5.z + mb.z * p6.z + mb.w * p7.z;
                s.w -= ma.x * p0.w + ma.y * p1.w + ma.z * p2.w + ma.w * p3.w
                     + mb.x * p4.w + mb.y * p5.w + mb.z * p6.w + mb.w * p7.w;
                *(float4*)(Sr + 4 * c) = s;
            }
        }
    }
    __syncthreads();

    // ---- back substitution, warp 0, all in registers ------------------------
    // solve L^T x = D^{-1} z :  x_r = z_r/d_r - sum_{k>r} L[k,r]*x_k
    if (tid < 32) {
        const int lane = tid;
        w0 = __fdividef(w0, S[lane * STR + lane]);
        w1 = __fdividef(w1, S[(lane + 32) * STR + (lane + 32)]);
        for (int k = NR - 1; k > 0; k--) {
            float xk = (k >= 32) ? __shfl_sync(0xffffffffu, w1, k - 32)
                                 : __shfl_sync(0xffffffffu, w0, k);
            const float* Lk = S + k * STR;
            if (lane < k)      w0 -= Lk[lane] * xk;
            if (lane + 32 < k) w1 -= Lk[lane + 32] * xk;
        }
        sol2[lane]      = w0;
        sol2[lane + 32] = w1;
    }
    __syncthreads();

    // ---- reload W (S region dead) + g = G^T l scatter -----------------------
    {
        const float4* gW4 = (const float4*)g_W;
        for (int idx = tid; idx < 1024; idx += 128) {
            float4 f = gW4[idx];
            int row = idx >> 4, c4 = (idx & 15) * 4;
            float* w = Wsm + row * WSTR + c4;
            w[0] = f.x; w[1] = f.y; w[2] = f.z; w[3] = f.w;
        }
    }
    gacc[tid] = 0.f;
    __syncthreads();
    if (tid < NC) {
        int c = tid;
        float wn = sol2[c];                // lambda_n
        float wt = sol2[NC + c];           // u = lambda+ - lambda-
        float wx = wn * en[c][0] + wt * et[c][0];
        float wy = wn * en[c][1] + wt * et[c][1];
        atomicAdd(&gacc[ii[c] * 2 + 0], -wx);
        atomicAdd(&gacc[ii[c] * 2 + 1], -wy);
        atomicAdd(&gacc[jj[c] * 2 + 0],  wx);
        atomicAdd(&gacc[jj[c] * 2 + 1],  wy);
    }
    __syncthreads();

    // ---- v_plus = W g - y  (identity: v + W(g - reg v) = Wg - y) -----------
    {
        int p = tid >> 1, s2 = tid & 1;
        float acc = 0.f;
        #pragma unroll 8
        for (int q = 0; q < 64; q++)
            acc += Wsm[p * WSTR + q] * gacc[q * 2 + s2];
        out[b * 256 + 128 + tid] = acc - ys[p][s2];
    }
}

// ---------------------------------------------------------------------------
extern "C" void kernel_launch(void* const* d_in, const int* in_sizes, int n_in,
                              void* d_out, int out_size) {
    const float* x    = (const float*)d_in[0];
    const float* v    = (const float*)d_in[1];
    const int*   cld  = (const int*)  d_in[2];
    const float* dist = (const float*)d_in[3];
    const float* mu   = (const float*)d_in[4];
    const float* cor  = (const float*)d_in[5];
    const float* Minv = (const float*)d_in[6];
    float* out = (float*)d_out;

    int bs = out_size / 256;

    prep_W2<<<16, 256>>>(Minv);
    solve_batch_kernel<<<bs, 128>>>(x, v, cld, dist, mu, cor, out);
}